// round 3
// baseline (speedup 1.0000x reference)
#include <cuda_runtime.h>
#include <math.h>

// Problem constants
#define B_      2
#define S_      2048
#define DMODEL  2048
#define NH      16
#define DH      128
#define DLAT    512
#define DR      64
#define DQK     192            // DH + DR
#define KVD     320            // DH + DR + DH
#define QFD     3072           // NH * DQK
#define KVFD    5120           // NH * KVD
#define ROWS    (B_*S_)        // 4096

// Scratch (device globals: allocation-free contract)
__device__ float g_kvlat[(size_t)ROWS * DLAT];
__device__ float g_qlat [(size_t)ROWS * DLAT];
__device__ float g_kvfull[(size_t)ROWS * KVFD];
__device__ float g_qfull [(size_t)ROWS * QFD];
__device__ float g_ctx   [(size_t)ROWS * DMODEL];

// ---------------------------------------------------------------------------
// SGEMM: C[M,N] = A[M,K] @ B[K,N], row-major, fp32.
// BM=BN=128, BK=8, 256 threads, 8x8 microtile (4+4 split for conflict-free smem).
// Requires M%128==0, N%128==0, K%8==0 (true for all our shapes).
// ---------------------------------------------------------------------------
__global__ __launch_bounds__(256) void sgemm_kernel(
    const float* __restrict__ A, const float* __restrict__ Bm,
    float* __restrict__ C, int M, int N, int K)
{
    __shared__ float As[8][128];
    __shared__ float Bs[8][128];

    const int tid = threadIdx.x;
    const int bx = blockIdx.x, by = blockIdx.y;
    const int ty = tid >> 4, tx = tid & 15;

    const float* Ablk = A + (size_t)by * 128 * K;
    const float* Bblk = Bm + (size_t)bx * 128;

    float acc[8][8];
#pragma unroll
    for (int i = 0; i < 8; i++)
#pragma unroll
        for (int j = 0; j < 8; j++) acc[i][j] = 0.f;

    const int arow = tid >> 1;         // 0..127
    const int ac4  = (tid & 1) * 4;    // 0 or 4
    const int brow = tid >> 5;         // 0..7
    const int bc4  = (tid & 31) * 4;   // 0..124

    for (int k0 = 0; k0 < K; k0 += 8) {
        // stage next tile through registers (global loads issue pre-sync)
        float4 av = *(const float4*)&Ablk[(size_t)arow * K + k0 + ac4];
        float4 bv = *(const float4*)&Bblk[(size_t)(k0 + brow) * N + bc4];
        __syncthreads();
        As[ac4 + 0][arow] = av.x;
        As[ac4 + 1][arow] = av.y;
        As[ac4 + 2][arow] = av.z;
        As[ac4 + 3][arow] = av.w;
        *(float4*)&Bs[brow][bc4] = bv;
        __syncthreads();

#pragma unroll
        for (int k = 0; k < 8; k++) {
            float4 a0 = *(const float4*)&As[k][ty * 4];
            float4 a1 = *(const float4*)&As[k][64 + ty * 4];
            float4 b0 = *(const float4*)&Bs[k][tx * 4];
            float4 b1 = *(const float4*)&Bs[k][64 + tx * 4];
            float ar[8] = {a0.x, a0.y, a0.z, a0.w, a1.x, a1.y, a1.z, a1.w};
            float br[8] = {b0.x, b0.y, b0.z, b0.w, b1.x, b1.y, b1.z, b1.w};
#pragma unroll
            for (int i = 0; i < 8; i++)
#pragma unroll
                for (int j = 0; j < 8; j++)
                    acc[i][j] += ar[i] * br[j];
        }
    }

#pragma unroll
    for (int i = 0; i < 8; i++) {
        int row = by * 128 + ((i < 4) ? (ty * 4 + i) : (64 + ty * 4 + i - 4));
        float4 c0 = make_float4(acc[i][0], acc[i][1], acc[i][2], acc[i][3]);
        float4 c1 = make_float4(acc[i][4], acc[i][5], acc[i][6], acc[i][7]);
        *(float4*)&C[(size_t)row * N + bx * 128 + tx * 4]      = c0;
        *(float4*)&C[(size_t)row * N + bx * 128 + 64 + tx * 4] = c1;
    }
}

// ---------------------------------------------------------------------------
// RoPE (in-place on q_full and kv_full rope slices).
// grid = ROWS, block = 512 (16 heads x 32 pair-lanes)
// out[j]    = x[j]*cos - x[j+32]*sin
// out[j+32] = x[j+32]*cos + x[j]*sin     (cos/sin share inv_freq[j])
// ---------------------------------------------------------------------------
__global__ __launch_bounds__(512) void rope_kernel()
{
    const int row = blockIdx.x;         // b*S + s
    const int s   = row & (S_ - 1);
    const int h   = threadIdx.x >> 5;
    const int j   = threadIdx.x & 31;

    // inv_freq = 10000^(-j/32)
    const float inv = expf(-(float)j * (9.210340371976184f / 32.f));
    const float f   = (float)s * inv;
    const float c   = cosf(f);
    const float sn  = sinf(f);

    {
        size_t base = (size_t)row * QFD + h * DQK + DH;
        float x1 = g_qfull[base + j];
        float x2 = g_qfull[base + 32 + j];
        g_qfull[base + j]      = x1 * c - x2 * sn;
        g_qfull[base + 32 + j] = x2 * c + x1 * sn;
    }
    {
        size_t base = (size_t)row * KVFD + h * KVD + DH;
        float x1 = g_kvfull[base + j];
        float x2 = g_kvfull[base + 32 + j];
        g_kvfull[base + j]      = x1 * c - x2 * sn;
        g_kvfull[base + 32 + j] = x2 * c + x1 * sn;
    }
}

// ---------------------------------------------------------------------------
// Flash attention (causal): grid (S/64, NH, B), 256 threads.
// BM=BN=64. Q scaled on load. Online softmax, one expf per score element.
// ---------------------------------------------------------------------------
#define BM 64
#define BN 64
#define QS_STRIDE 196          // 192 padded (stride mod 32 == 4 -> conflict free)
#define KS_STRIDE 196
#define SS_STRIDE 68           // 64 padded
#define ATTN_SMEM_FLOATS (BM*QS_STRIDE + BN*KS_STRIDE + BN*DH + BM*SS_STRIDE + 2*BM)
#define ATTN_SMEM_BYTES  (ATTN_SMEM_FLOATS * 4)

__global__ __launch_bounds__(256) void attn_kernel()
{
    extern __shared__ float sm[];
    float* Qs   = sm;
    float* Ks   = Qs + BM * QS_STRIDE;
    float* Vs   = Ks + BN * KS_STRIDE;
    float* Ss   = Vs + BN * DH;
    float* sm_m = Ss + BM * SS_STRIDE;
    float* sm_l = sm_m + BM;

    const int qt  = blockIdx.x;
    const int h   = blockIdx.y;
    const int b   = blockIdx.z;
    const int tid = threadIdx.x;
    const int qs0 = qt * BM;

    const int ty = tid >> 4, tx = tid & 15;      // score mapping: rows ty*4.., cols tx*4..
    const int rpv = tid >> 2, cpv = tid & 3;     // PV mapping: row rpv, col chunks cpv+4*uu

    const float scale = 0.07216878364870323f;    // 1/sqrt(192)

    // Load Q tile (scaled)
    for (int f = tid; f < BM * 48; f += 256) {
        int r = f / 48, v = f % 48;
        float4 q = *(const float4*)&g_qfull[(size_t)(b * S_ + qs0 + r) * QFD + h * DQK + v * 4];
        q.x *= scale; q.y *= scale; q.z *= scale; q.w *= scale;
        *(float4*)&Qs[r * QS_STRIDE + v * 4] = q;
    }

    float m_run = -1e30f, l_run = 0.f;
    float4 o[8];
#pragma unroll
    for (int u = 0; u < 8; u++) o[u] = make_float4(0.f, 0.f, 0.f, 0.f);

    __syncthreads();

    for (int kt = 0; kt <= qs0; kt += BN) {
        // Load K (192 dims) + V (128 dims) for 64 rows
        for (int f = tid; f < BN * 80; f += 256) {
            int r = f / 80, v = f % 80;
            float4 t = *(const float4*)&g_kvfull[(size_t)(b * S_ + kt + r) * KVFD + h * KVD + v * 4];
            if (v < 48) *(float4*)&Ks[r * KS_STRIDE + v * 4] = t;
            else        *(float4*)&Vs[r * DH + (v - 48) * 4] = t;
        }
        __syncthreads();

        // Scores: 4x4 microtile per thread
        float s[4][4];
#pragma unroll
        for (int i = 0; i < 4; i++)
#pragma unroll
            for (int j = 0; j < 4; j++) s[i][j] = 0.f;

#pragma unroll 4
        for (int k = 0; k < DQK; k += 4) {
            float4 qv[4], kv[4];
#pragma unroll
            for (int i = 0; i < 4; i++) qv[i] = *(const float4*)&Qs[(ty * 4 + i) * QS_STRIDE + k];
#pragma unroll
            for (int j = 0; j < 4; j++) kv[j] = *(const float4*)&Ks[(tx * 4 + j) * KS_STRIDE + k];
#pragma unroll
            for (int i = 0; i < 4; i++)
#pragma unroll
                for (int j = 0; j < 4; j++)
                    s[i][j] += qv[i].x * kv[j].x + qv[i].y * kv[j].y
                             + qv[i].z * kv[j].z + qv[i].w * kv[j].w;
        }

        if (kt == qs0) {  // diagonal tile: causal mask
#pragma unroll
            for (int i = 0; i < 4; i++)
#pragma unroll
                for (int j = 0; j < 4; j++)
                    if (tx * 4 + j > ty * 4 + i) s[i][j] = -1e30f;
        }

        // Row max via shfl across the 16 tx lanes sharing a ty
        float rm[4];
#pragma unroll
        for (int i = 0; i < 4; i++) {
            float m = fmaxf(fmaxf(s[i][0], s[i][1]), fmaxf(s[i][2], s[i][3]));
#pragma unroll
            for (int off = 8; off >= 1; off >>= 1)
                m = fmaxf(m, __shfl_xor_sync(0xffffffffu, m, off));
            rm[i] = m;
            if (tx == 0) sm_m[ty * 4 + i] = m;
        }
        __syncthreads();

        // Exp + row sum; store p into Ss
#pragma unroll
        for (int i = 0; i < 4; i++) {
            float m = rm[i];
            float4 p;
            p.x = __expf(s[i][0] - m);
            p.y = __expf(s[i][1] - m);
            p.z = __expf(s[i][2] - m);
            p.w = __expf(s[i][3] - m);
            *(float4*)&Ss[(ty * 4 + i) * SS_STRIDE + tx * 4] = p;
            float rs = p.x + p.y + p.z + p.w;
#pragma unroll
            for (int off = 8; off >= 1; off >>= 1)
                rs += __shfl_xor_sync(0xffffffffu, rs, off);
            if (tx == 0) sm_l[ty * 4 + i] = rs;
        }
        __syncthreads();

        // Online update + P@V
        {
            float mt = sm_m[rpv], lt = sm_l[rpv];
            float m_new = fmaxf(m_run, mt);
            float corr  = __expf(m_run - m_new);
            float fac   = __expf(mt - m_new);
            l_run = l_run * corr + lt * fac;
            m_run = m_new;
#pragma unroll
            for (int u = 0; u < 8; u++) {
                o[u].x *= corr; o[u].y *= corr; o[u].z *= corr; o[u].w *= corr;
            }
#pragma unroll 4
            for (int j = 0; j < BN; j++) {
                float p = Ss[rpv * SS_STRIDE + j] * fac;
#pragma unroll
                for (int u = 0; u < 8; u++) {
                    float4 v = *(const float4*)&Vs[j * DH + (cpv + 4 * u) * 4];
                    o[u].x += p * v.x; o[u].y += p * v.y;
                    o[u].z += p * v.z; o[u].w += p * v.w;
                }
            }
        }
        __syncthreads();   // protect Ks/Vs/Ss before next tile load
    }

    // Finalize and store context (layout [b,s,h*128+d])
    float inv_l = 1.f / l_run;
#pragma unroll
    for (int u = 0; u < 8; u++) {
        float4 w = o[u];
        w.x *= inv_l; w.y *= inv_l; w.z *= inv_l; w.w *= inv_l;
        *(float4*)&g_ctx[(size_t)(b * S_ + qs0 + rpv) * DMODEL + h * DH + (cpv + 4 * u) * 4] = w;
    }
}

// ---------------------------------------------------------------------------
// Launch
// ---------------------------------------------------------------------------
extern "C" void kernel_launch(void* const* d_in, const int* in_sizes, int n_in,
                              void* d_out, int out_size)
{
    (void)in_sizes; (void)n_in; (void)out_size;
    const float* x    = (const float*)d_in[0];
    const float* Wkvd = (const float*)d_in[1];
    const float* Wkvu = (const float*)d_in[2];
    const float* Wqd  = (const float*)d_in[3];
    const float* Wqu  = (const float*)d_in[4];
    const float* Wo   = (const float*)d_in[5];
    float* out = (float*)d_out;

    float *kvlat, *qlat, *kvfull, *qfull, *ctx;
    cudaGetSymbolAddress((void**)&kvlat,  g_kvlat);
    cudaGetSymbolAddress((void**)&qlat,   g_qlat);
    cudaGetSymbolAddress((void**)&kvfull, g_kvfull);
    cudaGetSymbolAddress((void**)&qfull,  g_qfull);
    cudaGetSymbolAddress((void**)&ctx,    g_ctx);

    dim3 t(256);
    // 1) down-projections
    sgemm_kernel<<<dim3(DLAT / 128, ROWS / 128), t>>>(x, Wkvd, kvlat, ROWS, DLAT, DMODEL);
    sgemm_kernel<<<dim3(DLAT / 128, ROWS / 128), t>>>(x, Wqd,  qlat,  ROWS, DLAT, DMODEL);
    // 2) up-projections
    sgemm_kernel<<<dim3(KVFD / 128, ROWS / 128), t>>>(kvlat, Wkvu, kvfull, ROWS, KVFD, DLAT);
    sgemm_kernel<<<dim3(QFD  / 128, ROWS / 128), t>>>(qlat,  Wqu,  qfull,  ROWS, QFD,  DLAT);
    // 3) RoPE in place
    rope_kernel<<<ROWS, 512>>>();
    // 4) attention
    cudaFuncSetAttribute(attn_kernel, cudaFuncAttributeMaxDynamicSharedMemorySize, ATTN_SMEM_BYTES);
    attn_kernel<<<dim3(S_ / BM, NH, B_), 256, ATTN_SMEM_BYTES>>>();
    // 5) output projection
    sgemm_kernel<<<dim3(DMODEL / 128, ROWS / 128), t>>>(ctx, Wo, out, ROWS, DMODEL, DMODEL);
}

// round 5
// speedup vs baseline: 1.5203x; 1.5203x over previous
#include <cuda_runtime.h>
#include <math.h>

// Problem constants
#define B_      2
#define S_      2048
#define DMODEL  2048
#define NH      16
#define DH      128
#define DLAT    512
#define DR      64
#define DQK     192            // DH + DR
#define KVD     320            // DH + DR + DH
#define QFD     3072           // NH * DQK
#define KVFD    5120           // NH * KVD
#define ROWS    (B_*S_)        // 4096

// Scratch (device globals: allocation-free contract)
__device__ float g_kvlat[(size_t)ROWS * DLAT];
__device__ float g_qlat [(size_t)ROWS * DLAT];
__device__ float g_kvfull[(size_t)ROWS * KVFD];
__device__ float g_qfull [(size_t)ROWS * QFD];
__device__ float g_ctx   [(size_t)ROWS * DMODEL];

// ---------------------------------------------------------------------------
// SGEMM: C[M,N] = A[M,K] @ B[K,N], row-major, fp32.
// BM=BN=128, BK=8, 256 threads, 8x8 microtile. Double-buffered smem:
// one __syncthreads per K-step.
// ---------------------------------------------------------------------------
__global__ __launch_bounds__(256) void sgemm_kernel(
    const float* __restrict__ A, const float* __restrict__ Bm,
    float* __restrict__ C, int M, int N, int K)
{
    __shared__ float As[2][8][128];
    __shared__ float Bs[2][8][128];

    const int tid = threadIdx.x;
    const int bx = blockIdx.x, by = blockIdx.y;
    const int ty = tid >> 4, tx = tid & 15;

    const float* Ablk = A + (size_t)by * 128 * K;
    const float* Bblk = Bm + (size_t)bx * 128;

    float acc[8][8];
#pragma unroll
    for (int i = 0; i < 8; i++)
#pragma unroll
        for (int j = 0; j < 8; j++) acc[i][j] = 0.f;

    const int arow = tid >> 1;         // 0..127
    const int ac4  = (tid & 1) * 4;    // 0 or 4
    const int brow = tid >> 5;         // 0..7
    const int bc4  = (tid & 31) * 4;   // 0..124

    // Prologue: stage tile 0
    {
        float4 av = *(const float4*)&Ablk[(size_t)arow * K + ac4];
        float4 bv = *(const float4*)&Bblk[(size_t)brow * N + bc4];
        As[0][ac4 + 0][arow] = av.x;
        As[0][ac4 + 1][arow] = av.y;
        As[0][ac4 + 2][arow] = av.z;
        As[0][ac4 + 3][arow] = av.w;
        *(float4*)&Bs[0][brow][bc4] = bv;
    }
    __syncthreads();

    int buf = 0;
    for (int k0 = 0; k0 < K; k0 += 8) {
        float4 av2, bv2;
        const bool more = (k0 + 8) < K;
        if (more) {
            av2 = *(const float4*)&Ablk[(size_t)arow * K + k0 + 8 + ac4];
            bv2 = *(const float4*)&Bblk[(size_t)(k0 + 8 + brow) * N + bc4];
        }

#pragma unroll
        for (int k = 0; k < 8; k++) {
            float4 a0 = *(const float4*)&As[buf][k][ty * 4];
            float4 a1 = *(const float4*)&As[buf][k][64 + ty * 4];
            float4 b0 = *(const float4*)&Bs[buf][k][tx * 4];
            float4 b1 = *(const float4*)&Bs[buf][k][64 + tx * 4];
            float ar[8] = {a0.x, a0.y, a0.z, a0.w, a1.x, a1.y, a1.z, a1.w};
            float br[8] = {b0.x, b0.y, b0.z, b0.w, b1.x, b1.y, b1.z, b1.w};
#pragma unroll
            for (int i = 0; i < 8; i++)
#pragma unroll
                for (int j = 0; j < 8; j++)
                    acc[i][j] += ar[i] * br[j];
        }

        if (more) {
            As[buf ^ 1][ac4 + 0][arow] = av2.x;
            As[buf ^ 1][ac4 + 1][arow] = av2.y;
            As[buf ^ 1][ac4 + 2][arow] = av2.z;
            As[buf ^ 1][ac4 + 3][arow] = av2.w;
            *(float4*)&Bs[buf ^ 1][brow][bc4] = bv2;
            __syncthreads();
            buf ^= 1;
        }
    }

#pragma unroll
    for (int i = 0; i < 8; i++) {
        int row = by * 128 + ((i < 4) ? (ty * 4 + i) : (64 + ty * 4 + i - 4));
        float4 c0 = make_float4(acc[i][0], acc[i][1], acc[i][2], acc[i][3]);
        float4 c1 = make_float4(acc[i][4], acc[i][5], acc[i][6], acc[i][7]);
        *(float4*)&C[(size_t)row * N + bx * 128 + tx * 4]      = c0;
        *(float4*)&C[(size_t)row * N + bx * 128 + 64 + tx * 4] = c1;
    }
}

// ---------------------------------------------------------------------------
// RoPE (in-place on q_full and kv_full rope slices).
// ---------------------------------------------------------------------------
__global__ __launch_bounds__(512) void rope_kernel()
{
    const int row = blockIdx.x;         // b*S + s
    const int s   = row & (S_ - 1);
    const int h   = threadIdx.x >> 5;
    const int j   = threadIdx.x & 31;

    const float inv = expf(-(float)j * (9.210340371976184f / 32.f));
    const float f   = (float)s * inv;
    const float c   = cosf(f);
    const float sn  = sinf(f);

    {
        size_t base = (size_t)row * QFD + h * DQK + DH;
        float x1 = g_qfull[base + j];
        float x2 = g_qfull[base + 32 + j];
        g_qfull[base + j]      = x1 * c - x2 * sn;
        g_qfull[base + 32 + j] = x2 * c + x1 * sn;
    }
    {
        size_t base = (size_t)row * KVFD + h * KVD + DH;
        float x1 = g_kvfull[base + j];
        float x2 = g_kvfull[base + 32 + j];
        g_kvfull[base + j]      = x1 * c - x2 * sn;
        g_kvfull[base + 32 + j] = x2 * c + x1 * sn;
    }
}

// ---------------------------------------------------------------------------
// Flash attention v2 (causal): BM=128, BN=64, 256 threads.
// Score microtile 8x4 (rows ry*4+i / 64+ry*4+i, cols cx+16*j),
// PV microtile 8x8 (cols cx*4 / 64+cx*4). m/l state fully in registers.
// ---------------------------------------------------------------------------
#define ABM 128
#define ABN 64
#define KSTR 196               // 192 padded (Q/K row stride)
#define VSTR 128
#define SSTR 68                // 64 padded
#define ATTN_SMEM_FLOATS (ABM*KSTR + ABN*KSTR + ABN*VSTR + ABM*SSTR)
#define ATTN_SMEM_BYTES  (ATTN_SMEM_FLOATS * 4)

__global__ __launch_bounds__(256, 1) void attn_kernel()
{
    extern __shared__ float sm[];
    float* Qs = sm;                    // [128][196]
    float* Ks = Qs + ABM * KSTR;       // [64][196]
    float* Vs = Ks + ABN * KSTR;       // [64][128]
    float* Ss = Vs + ABN * VSTR;       // [128][68]

    const int qt  = gridDim.x - 1 - blockIdx.x;   // long blocks first
    const int h   = blockIdx.y;
    const int b   = blockIdx.z;
    const int tid = threadIdx.x;
    const int ry  = tid >> 4;          // 0..15
    const int cx  = tid & 15;          // 0..15
    const int qs0 = qt * ABM;

    const float scale = 0.07216878364870323f;     // 1/sqrt(192)

    int rows[8];
#pragma unroll
    for (int i = 0; i < 8; i++)
        rows[i] = (i < 4) ? (ry * 4 + i) : (64 + ry * 4 + (i - 4));

    // Load Q tile (scaled)
    for (int f = tid; f < ABM * 48; f += 256) {
        int r = f / 48, d4 = f % 48;
        float4 q = *(const float4*)&g_qfull[(size_t)(b * S_ + qs0 + r) * QFD + h * DQK + d4 * 4];
        q.x *= scale; q.y *= scale; q.z *= scale; q.w *= scale;
        *(float4*)&Qs[r * KSTR + d4 * 4] = q;
    }

    float m_run[8], l_run[8], o[8][8];
#pragma unroll
    for (int i = 0; i < 8; i++) {
        m_run[i] = -1e30f; l_run[i] = 0.f;
#pragma unroll
        for (int jj = 0; jj < 8; jj++) o[i][jj] = 0.f;
    }

    __syncthreads();

    for (int kt = 0; kt <= qs0 + 64; kt += ABN) {
        // Load K (192 dims) + V (128 dims) for 64 key rows
        for (int f = tid; f < ABN * 80; f += 256) {
            int r = f / 80, v = f % 80;
            float4 t = *(const float4*)&g_kvfull[(size_t)(b * S_ + kt + r) * KVFD + h * KVD + v * 4];
            if (v < 48) *(float4*)&Ks[r * KSTR + v * 4] = t;
            else        *(float4*)&Vs[r * VSTR + (v - 48) * 4] = t;
        }
        __syncthreads();

        // ---- scores: 8x4 per thread ----
        float s[8][4];
#pragma unroll
        for (int i = 0; i < 8; i++)
#pragma unroll
            for (int j = 0; j < 4; j++) s[i][j] = 0.f;

#pragma unroll 4
        for (int k = 0; k < DQK; k += 4) {
            float4 kv[4];
#pragma unroll
            for (int j = 0; j < 4; j++)
                kv[j] = *(const float4*)&Ks[(cx + 16 * j) * KSTR + k];
#pragma unroll
            for (int i = 0; i < 8; i++) {
                float4 qv = *(const float4*)&Qs[rows[i] * KSTR + k];
#pragma unroll
                for (int j = 0; j < 4; j++)
                    s[i][j] += qv.x * kv[j].x + qv.y * kv[j].y
                             + qv.z * kv[j].z + qv.w * kv[j].w;
            }
        }

        // causal mask (only the two diagonal-straddling tiles)
        if (kt >= qs0) {
#pragma unroll
            for (int i = 0; i < 8; i++)
#pragma unroll
                for (int j = 0; j < 4; j++)
                    if (kt + cx + 16 * j > qs0 + rows[i]) s[i][j] = -1e30f;
        }

        // ---- online softmax (per-row state in registers) ----
#pragma unroll
        for (int i = 0; i < 8; i++) {
            float rm = fmaxf(fmaxf(s[i][0], s[i][1]), fmaxf(s[i][2], s[i][3]));
            rm = fmaxf(rm, __shfl_xor_sync(0xffffffffu, rm, 1));
            rm = fmaxf(rm, __shfl_xor_sync(0xffffffffu, rm, 2));
            rm = fmaxf(rm, __shfl_xor_sync(0xffffffffu, rm, 4));
            rm = fmaxf(rm, __shfl_xor_sync(0xffffffffu, rm, 8));
            float m_new = fmaxf(m_run[i], rm);
            float p0 = __expf(s[i][0] - m_new);
            float p1 = __expf(s[i][1] - m_new);
            float p2 = __expf(s[i][2] - m_new);
            float p3 = __expf(s[i][3] - m_new);
            float rs = p0 + p1 + p2 + p3;
            rs += __shfl_xor_sync(0xffffffffu, rs, 1);
            rs += __shfl_xor_sync(0xffffffffu, rs, 2);
            rs += __shfl_xor_sync(0xffffffffu, rs, 4);
            rs += __shfl_xor_sync(0xffffffffu, rs, 8);
            float corr = __expf(m_run[i] - m_new);
            l_run[i] = l_run[i] * corr + rs;
            m_run[i] = m_new;
#pragma unroll
            for (int jj = 0; jj < 8; jj++) o[i][jj] *= corr;
            Ss[rows[i] * SSTR + cx]      = p0;
            Ss[rows[i] * SSTR + cx + 16] = p1;
            Ss[rows[i] * SSTR + cx + 32] = p2;
            Ss[rows[i] * SSTR + cx + 48] = p3;
        }
        __syncthreads();

        // ---- PV: 8x8 per thread ----
#pragma unroll 2
        for (int j4 = 0; j4 < 16; j4++) {
            float4 pv[8];
#pragma unroll
            for (int i = 0; i < 8; i++)
                pv[i] = *(const float4*)&Ss[rows[i] * SSTR + j4 * 4];
#pragma unroll
            for (int jj = 0; jj < 4; jj++) {
                float4 v0 = *(const float4*)&Vs[(j4 * 4 + jj) * VSTR + cx * 4];
                float4 v1 = *(const float4*)&Vs[(j4 * 4 + jj) * VSTR + 64 + cx * 4];
#pragma unroll
                for (int i = 0; i < 8; i++) {
                    float p = (jj == 0) ? pv[i].x : (jj == 1) ? pv[i].y
                            : (jj == 2) ? pv[i].z : pv[i].w;
                    o[i][0] += p * v0.x; o[i][1] += p * v0.y;
                    o[i][2] += p * v0.z; o[i][3] += p * v0.w;
                    o[i][4] += p * v1.x; o[i][5] += p * v1.y;
                    o[i][6] += p * v1.z; o[i][7] += p * v1.w;
                }
            }
        }
        __syncthreads();   // protect Ks/Vs/Ss before next tile load
    }

    // Finalize and store context (layout [b,s,h*128+d])
#pragma unroll
    for (int i = 0; i < 8; i++) {
        float inv_l = 1.f / l_run[i];
        float4 c0 = make_float4(o[i][0] * inv_l, o[i][1] * inv_l,
                                o[i][2] * inv_l, o[i][3] * inv_l);
        float4 c1 = make_float4(o[i][4] * inv_l, o[i][5] * inv_l,
                                o[i][6] * inv_l, o[i][7] * inv_l);
        size_t base = (size_t)(b * S_ + qs0 + rows[i]) * DMODEL + h * DH;
        *(float4*)&g_ctx[base + cx * 4]      = c0;
        *(float4*)&g_ctx[base + 64 + cx * 4] = c1;
    }
}

// ---------------------------------------------------------------------------
// Launch
// ---------------------------------------------------------------------------
extern "C" void kernel_launch(void* const* d_in, const int* in_sizes, int n_in,
                              void* d_out, int out_size)
{
    (void)in_sizes; (void)n_in; (void)out_size;
    const float* x    = (const float*)d_in[0];
    const float* Wkvd = (const float*)d_in[1];
    const float* Wkvu = (const float*)d_in[2];
    const float* Wqd  = (const float*)d_in[3];
    const float* Wqu  = (const float*)d_in[4];
    const float* Wo   = (const float*)d_in[5];
    float* out = (float*)d_out;

    float *kvlat, *qlat, *kvfull, *qfull, *ctx;
    cudaGetSymbolAddress((void**)&kvlat,  g_kvlat);
    cudaGetSymbolAddress((void**)&qlat,   g_qlat);
    cudaGetSymbolAddress((void**)&kvfull, g_kvfull);
    cudaGetSymbolAddress((void**)&qfull,  g_qfull);
    cudaGetSymbolAddress((void**)&ctx,    g_ctx);

    dim3 t(256);
    // 1) down-projections
    sgemm_kernel<<<dim3(DLAT / 128, ROWS / 128), t>>>(x, Wkvd, kvlat, ROWS, DLAT, DMODEL);
    sgemm_kernel<<<dim3(DLAT / 128, ROWS / 128), t>>>(x, Wqd,  qlat,  ROWS, DLAT, DMODEL);
    // 2) up-projections
    sgemm_kernel<<<dim3(KVFD / 128, ROWS / 128), t>>>(kvlat, Wkvu, kvfull, ROWS, KVFD, DLAT);
    sgemm_kernel<<<dim3(QFD  / 128, ROWS / 128), t>>>(qlat,  Wqu,  qfull,  ROWS, QFD,  DLAT);
    // 3) RoPE in place
    rope_kernel<<<ROWS, 512>>>();
    // 4) attention
    cudaFuncSetAttribute(attn_kernel, cudaFuncAttributeMaxDynamicSharedMemorySize, ATTN_SMEM_BYTES);
    attn_kernel<<<dim3(S_ / ABM, NH, B_), 256, ATTN_SMEM_BYTES>>>();
    // 5) output projection
    sgemm_kernel<<<dim3(DMODEL / 128, ROWS / 128), t>>>(ctx, Wo, out, ROWS, DMODEL, DMODEL);
}

// round 6
// speedup vs baseline: 1.7721x; 1.1656x over previous
#include <cuda_runtime.h>
#include <math.h>

// Problem constants
#define B_      2
#define S_      2048
#define DMODEL  2048
#define NH      16
#define DH      128
#define DLAT    512
#define DR      64
#define DQK     192            // DH + DR
#define KVD     320            // DH + DR + DH
#define QFD     3072           // NH * DQK
#define KVFD    5120           // NH * KVD
#define ROWS    (B_*S_)        // 4096

typedef unsigned long long u64;

// ---- packed f32x2 helpers (Blackwell FFMA2 path) ----
__device__ __forceinline__ u64 pack2(float lo, float hi) {
    u64 r; asm("mov.b64 %0, {%1, %2};" : "=l"(r) : "f"(lo), "f"(hi)); return r;
}
__device__ __forceinline__ void unpack2(u64 v, float& lo, float& hi) {
    asm("mov.b64 {%0, %1}, %2;" : "=f"(lo), "=f"(hi) : "l"(v));
}
__device__ __forceinline__ void ffma2(u64& d, u64 a, u64 b) {
    asm("fma.rn.f32x2 %0, %1, %2, %0;" : "+l"(d) : "l"(a), "l"(b));
}
__device__ __forceinline__ u64 mul2(u64 a, u64 b) {
    u64 d; asm("mul.rn.f32x2 %0, %1, %2;" : "=l"(d) : "l"(a), "l"(b)); return d;
}

// Scratch (device globals: allocation-free contract)
__device__ float g_kvlat[(size_t)ROWS * DLAT];
__device__ float g_qlat [(size_t)ROWS * DLAT];
__device__ float g_kvfull[(size_t)ROWS * KVFD];
__device__ float g_qfull [(size_t)ROWS * QFD];
__device__ float g_ctx   [(size_t)ROWS * DMODEL];

// ---------------------------------------------------------------------------
// SGEMM: C[M,N] = A[M,K] @ B[K,N], row-major, fp32, FFMA2 accumulation.
// BM=BN=128, BK=8, 256 threads, 8x8 microtile (j-axis packed into f32x2).
// ---------------------------------------------------------------------------
__global__ __launch_bounds__(256) void sgemm_kernel(
    const float* __restrict__ A, const float* __restrict__ Bm,
    float* __restrict__ C, int M, int N, int K)
{
    __shared__ float As[2][8][128];
    __shared__ float Bs[2][8][128];

    const int tid = threadIdx.x;
    const int bx = blockIdx.x, by = blockIdx.y;
    const int ty = tid >> 4, tx = tid & 15;

    const float* Ablk = A + (size_t)by * 128 * K;
    const float* Bblk = Bm + (size_t)bx * 128;

    u64 acc2[8][4];
#pragma unroll
    for (int i = 0; i < 8; i++)
#pragma unroll
        for (int j = 0; j < 4; j++) acc2[i][j] = 0ull;

    const int arow = tid >> 1;         // 0..127
    const int ac4  = (tid & 1) * 4;    // 0 or 4
    const int brow = tid >> 5;         // 0..7
    const int bc4  = (tid & 31) * 4;   // 0..124

    // Prologue: stage tile 0
    {
        float4 av = *(const float4*)&Ablk[(size_t)arow * K + ac4];
        float4 bv = *(const float4*)&Bblk[(size_t)brow * N + bc4];
        As[0][ac4 + 0][arow] = av.x;
        As[0][ac4 + 1][arow] = av.y;
        As[0][ac4 + 2][arow] = av.z;
        As[0][ac4 + 3][arow] = av.w;
        *(float4*)&Bs[0][brow][bc4] = bv;
    }
    __syncthreads();

    int buf = 0;
    for (int k0 = 0; k0 < K; k0 += 8) {
        float4 av2, bv2;
        const bool more = (k0 + 8) < K;
        if (more) {
            av2 = *(const float4*)&Ablk[(size_t)arow * K + k0 + 8 + ac4];
            bv2 = *(const float4*)&Bblk[(size_t)(k0 + 8 + brow) * N + bc4];
        }

#pragma unroll
        for (int k = 0; k < 8; k++) {
            float4 a0 = *(const float4*)&As[buf][k][ty * 4];
            float4 a1 = *(const float4*)&As[buf][k][64 + ty * 4];
            ulonglong2 bq0 = *(const ulonglong2*)&Bs[buf][k][tx * 4];
            ulonglong2 bq1 = *(const ulonglong2*)&Bs[buf][k][64 + tx * 4];
            u64 b2[4] = {bq0.x, bq0.y, bq1.x, bq1.y};
            float ar[8] = {a0.x, a0.y, a0.z, a0.w, a1.x, a1.y, a1.z, a1.w};
#pragma unroll
            for (int i = 0; i < 8; i++) {
                u64 ad = pack2(ar[i], ar[i]);
#pragma unroll
                for (int j = 0; j < 4; j++)
                    ffma2(acc2[i][j], ad, b2[j]);
            }
        }

        if (more) {
            As[buf ^ 1][ac4 + 0][arow] = av2.x;
            As[buf ^ 1][ac4 + 1][arow] = av2.y;
            As[buf ^ 1][ac4 + 2][arow] = av2.z;
            As[buf ^ 1][ac4 + 3][arow] = av2.w;
            *(float4*)&Bs[buf ^ 1][brow][bc4] = bv2;
            __syncthreads();
            buf ^= 1;
        }
    }

#pragma unroll
    for (int i = 0; i < 8; i++) {
        int row = by * 128 + ((i < 4) ? (ty * 4 + i) : (64 + ty * 4 + i - 4));
        float4 c0, c1;
        unpack2(acc2[i][0], c0.x, c0.y);
        unpack2(acc2[i][1], c0.z, c0.w);
        unpack2(acc2[i][2], c1.x, c1.y);
        unpack2(acc2[i][3], c1.z, c1.w);
        *(float4*)&C[(size_t)row * N + bx * 128 + tx * 4]      = c0;
        *(float4*)&C[(size_t)row * N + bx * 128 + 64 + tx * 4] = c1;
    }
}

// ---------------------------------------------------------------------------
// RoPE (in-place on q_full and kv_full rope slices).
// ---------------------------------------------------------------------------
__global__ __launch_bounds__(512) void rope_kernel()
{
    const int row = blockIdx.x;         // b*S + s
    const int s   = row & (S_ - 1);
    const int h   = threadIdx.x >> 5;
    const int j   = threadIdx.x & 31;

    const float inv = expf(-(float)j * (9.210340371976184f / 32.f));
    const float f   = (float)s * inv;
    const float c   = cosf(f);
    const float sn  = sinf(f);

    {
        size_t base = (size_t)row * QFD + h * DQK + DH;
        float x1 = g_qfull[base + j];
        float x2 = g_qfull[base + 32 + j];
        g_qfull[base + j]      = x1 * c - x2 * sn;
        g_qfull[base + 32 + j] = x2 * c + x1 * sn;
    }
    {
        size_t base = (size_t)row * KVFD + h * KVD + DH;
        float x1 = g_kvfull[base + j];
        float x2 = g_kvfull[base + 32 + j];
        g_kvfull[base + j]      = x1 * c - x2 * sn;
        g_kvfull[base + 32 + j] = x2 * c + x1 * sn;
    }
}

// ---------------------------------------------------------------------------
// Flash attention (causal): BM=128, BN=64, 256 threads, FFMA2.
// QK: packed along reduction k (no dups). PV: packed along output cols.
// ---------------------------------------------------------------------------
#define ABM 128
#define ABN 64
#define KSTR 196               // 192 padded (Q/K row stride)
#define VSTR 128
#define SSTR 68                // 64 padded
#define ATTN_SMEM_FLOATS (ABM*KSTR + ABN*KSTR + ABN*VSTR + ABM*SSTR)
#define ATTN_SMEM_BYTES  (ATTN_SMEM_FLOATS * 4)

__global__ __launch_bounds__(256, 1) void attn_kernel()
{
    extern __shared__ float sm[];
    float* Qs = sm;                    // [128][196]
    float* Ks = Qs + ABM * KSTR;       // [64][196]
    float* Vs = Ks + ABN * KSTR;       // [64][128]
    float* Ss = Vs + ABN * VSTR;       // [128][68]

    const int qt  = gridDim.x - 1 - blockIdx.x;   // long blocks first
    const int h   = blockIdx.y;
    const int b   = blockIdx.z;
    const int tid = threadIdx.x;
    const int ry  = tid >> 4;          // 0..15
    const int cx  = tid & 15;          // 0..15
    const int qs0 = qt * ABM;

    const float scale = 0.07216878364870323f;     // 1/sqrt(192)

    int rows[8];
#pragma unroll
    for (int i = 0; i < 8; i++)
        rows[i] = (i < 4) ? (ry * 4 + i) : (64 + ry * 4 + (i - 4));

    // Load Q tile (scaled)
    for (int f = tid; f < ABM * 48; f += 256) {
        int r = f / 48, d4 = f % 48;
        float4 q = *(const float4*)&g_qfull[(size_t)(b * S_ + qs0 + r) * QFD + h * DQK + d4 * 4];
        q.x *= scale; q.y *= scale; q.z *= scale; q.w *= scale;
        *(float4*)&Qs[r * KSTR + d4 * 4] = q;
    }

    float m_run[8], l_run[8];
    u64 o2[8][4];                      // packed col-pairs: (0,1)(2,3)(64,65)(66,67) blocks
#pragma unroll
    for (int i = 0; i < 8; i++) {
        m_run[i] = -1e30f; l_run[i] = 0.f;
#pragma unroll
        for (int t = 0; t < 4; t++) o2[i][t] = 0ull;
    }

    __syncthreads();

    for (int kt = 0; kt <= qs0 + 64; kt += ABN) {
        // Load K (192 dims) + V (128 dims) for 64 key rows
        for (int f = tid; f < ABN * 80; f += 256) {
            int r = f / 80, v = f % 80;
            float4 t = *(const float4*)&g_kvfull[(size_t)(b * S_ + kt + r) * KVFD + h * KVD + v * 4];
            if (v < 48) *(float4*)&Ks[r * KSTR + v * 4] = t;
            else        *(float4*)&Vs[r * VSTR + (v - 48) * 4] = t;
        }
        __syncthreads();

        // ---- scores: 8x4 per thread, packed along k (even/odd lanes) ----
        u64 s2[8][4];
#pragma unroll
        for (int i = 0; i < 8; i++)
#pragma unroll
            for (int j = 0; j < 4; j++) s2[i][j] = 0ull;

#pragma unroll 2
        for (int k = 0; k < DQK; k += 4) {
            ulonglong2 kv2[4];
#pragma unroll
            for (int j = 0; j < 4; j++)
                kv2[j] = *(const ulonglong2*)&Ks[(cx + 16 * j) * KSTR + k];
#pragma unroll
            for (int i = 0; i < 8; i++) {
                ulonglong2 qv2 = *(const ulonglong2*)&Qs[rows[i] * KSTR + k];
#pragma unroll
                for (int j = 0; j < 4; j++) {
                    ffma2(s2[i][j], qv2.x, kv2[j].x);
                    ffma2(s2[i][j], qv2.y, kv2[j].y);
                }
            }
        }

        float s[8][4];
#pragma unroll
        for (int i = 0; i < 8; i++)
#pragma unroll
            for (int j = 0; j < 4; j++) {
                float lo, hi; unpack2(s2[i][j], lo, hi);
                s[i][j] = lo + hi;
            }

        // causal mask (only the two diagonal-straddling tiles)
        if (kt >= qs0) {
#pragma unroll
            for (int i = 0; i < 8; i++)
#pragma unroll
                for (int j = 0; j < 4; j++)
                    if (kt + cx + 16 * j > qs0 + rows[i]) s[i][j] = -1e30f;
        }

        // ---- online softmax (per-row state in registers) ----
#pragma unroll
        for (int i = 0; i < 8; i++) {
            float rm = fmaxf(fmaxf(s[i][0], s[i][1]), fmaxf(s[i][2], s[i][3]));
            rm = fmaxf(rm, __shfl_xor_sync(0xffffffffu, rm, 1));
            rm = fmaxf(rm, __shfl_xor_sync(0xffffffffu, rm, 2));
            rm = fmaxf(rm, __shfl_xor_sync(0xffffffffu, rm, 4));
            rm = fmaxf(rm, __shfl_xor_sync(0xffffffffu, rm, 8));
            float m_new = fmaxf(m_run[i], rm);
            float p0 = __expf(s[i][0] - m_new);
            float p1 = __expf(s[i][1] - m_new);
            float p2 = __expf(s[i][2] - m_new);
            float p3 = __expf(s[i][3] - m_new);
            float rs = p0 + p1 + p2 + p3;
            rs += __shfl_xor_sync(0xffffffffu, rs, 1);
            rs += __shfl_xor_sync(0xffffffffu, rs, 2);
            rs += __shfl_xor_sync(0xffffffffu, rs, 4);
            rs += __shfl_xor_sync(0xffffffffu, rs, 8);
            float corr = __expf(m_run[i] - m_new);
            l_run[i] = l_run[i] * corr + rs;
            m_run[i] = m_new;
            u64 c2 = pack2(corr, corr);
#pragma unroll
            for (int t = 0; t < 4; t++) o2[i][t] = mul2(o2[i][t], c2);
            Ss[rows[i] * SSTR + cx]      = p0;
            Ss[rows[i] * SSTR + cx + 16] = p1;
            Ss[rows[i] * SSTR + cx + 32] = p2;
            Ss[rows[i] * SSTR + cx + 48] = p3;
        }
        __syncthreads();

        // ---- PV: 8 rows x 8 cols per thread, cols packed as f32x2 ----
#pragma unroll 2
        for (int j4 = 0; j4 < 16; j4++) {
            float4 pv[8];
#pragma unroll
            for (int i = 0; i < 8; i++)
                pv[i] = *(const float4*)&Ss[rows[i] * SSTR + j4 * 4];
#pragma unroll
            for (int jj = 0; jj < 4; jj++) {
                ulonglong2 v0 = *(const ulonglong2*)&Vs[(j4 * 4 + jj) * VSTR + cx * 4];
                ulonglong2 v1 = *(const ulonglong2*)&Vs[(j4 * 4 + jj) * VSTR + 64 + cx * 4];
#pragma unroll
                for (int i = 0; i < 8; i++) {
                    float p = (jj == 0) ? pv[i].x : (jj == 1) ? pv[i].y
                            : (jj == 2) ? pv[i].z : pv[i].w;
                    u64 pd = pack2(p, p);
                    ffma2(o2[i][0], pd, v0.x);
                    ffma2(o2[i][1], pd, v0.y);
                    ffma2(o2[i][2], pd, v1.x);
                    ffma2(o2[i][3], pd, v1.y);
                }
            }
        }
        __syncthreads();   // protect Ks/Vs/Ss before next tile load
    }

    // Finalize and store context (layout [b,s,h*128+d])
#pragma unroll
    for (int i = 0; i < 8; i++) {
        float inv_l = 1.f / l_run[i];
        float4 c0, c1;
        unpack2(o2[i][0], c0.x, c0.y);
        unpack2(o2[i][1], c0.z, c0.w);
        unpack2(o2[i][2], c1.x, c1.y);
        unpack2(o2[i][3], c1.z, c1.w);
        c0.x *= inv_l; c0.y *= inv_l; c0.z *= inv_l; c0.w *= inv_l;
        c1.x *= inv_l; c1.y *= inv_l; c1.z *= inv_l; c1.w *= inv_l;
        size_t base = (size_t)(b * S_ + qs0 + rows[i]) * DMODEL + h * DH;
        *(float4*)&g_ctx[base + cx * 4]      = c0;
        *(float4*)&g_ctx[base + 64 + cx * 4] = c1;
    }
}

// ---------------------------------------------------------------------------
// Launch
// ---------------------------------------------------------------------------
extern "C" void kernel_launch(void* const* d_in, const int* in_sizes, int n_in,
                              void* d_out, int out_size)
{
    (void)in_sizes; (void)n_in; (void)out_size;
    const float* x    = (const float*)d_in[0];
    const float* Wkvd = (const float*)d_in[1];
    const float* Wkvu = (const float*)d_in[2];
    const float* Wqd  = (const float*)d_in[3];
    const float* Wqu  = (const float*)d_in[4];
    const float* Wo   = (const float*)d_in[5];
    float* out = (float*)d_out;

    float *kvlat, *qlat, *kvfull, *qfull, *ctx;
    cudaGetSymbolAddress((void**)&kvlat,  g_kvlat);
    cudaGetSymbolAddress((void**)&qlat,   g_qlat);
    cudaGetSymbolAddress((void**)&kvfull, g_kvfull);
    cudaGetSymbolAddress((void**)&qfull,  g_qfull);
    cudaGetSymbolAddress((void**)&ctx,    g_ctx);

    dim3 t(256);
    // 1) down-projections
    sgemm_kernel<<<dim3(DLAT / 128, ROWS / 128), t>>>(x, Wkvd, kvlat, ROWS, DLAT, DMODEL);
    sgemm_kernel<<<dim3(DLAT / 128, ROWS / 128), t>>>(x, Wqd,  qlat,  ROWS, DLAT, DMODEL);
    // 2) up-projections
    sgemm_kernel<<<dim3(KVFD / 128, ROWS / 128), t>>>(kvlat, Wkvu, kvfull, ROWS, KVFD, DLAT);
    sgemm_kernel<<<dim3(QFD  / 128, ROWS / 128), t>>>(qlat,  Wqu,  qfull,  ROWS, QFD,  DLAT);
    // 3) RoPE in place
    rope_kernel<<<ROWS, 512>>>();
    // 4) attention
    cudaFuncSetAttribute(attn_kernel, cudaFuncAttributeMaxDynamicSharedMemorySize, ATTN_SMEM_BYTES);
    attn_kernel<<<dim3(S_ / ABM, NH, B_), 256, ATTN_SMEM_BYTES>>>();
    // 5) output projection
    sgemm_kernel<<<dim3(DMODEL / 128, ROWS / 128), t>>>(ctx, Wo, out, ROWS, DMODEL, DMODEL);
}

// round 8
// speedup vs baseline: 2.1695x; 1.2243x over previous
#include <cuda_runtime.h>
#include <cuda_bf16.h>
#include <math.h>
#include <stdint.h>

// Problem constants
#define B_      2
#define S_      2048
#define DMODEL  2048
#define NH      16
#define DH      128
#define DLAT    512
#define DR      64
#define DQK     192            // DH + DR
#define KVD     320            // DH + DR + DH
#define QFD     3072           // NH * DQK
#define KVFD    5120           // NH * KVD
#define ROWS    (B_*S_)        // 4096

typedef unsigned long long u64;

// ---- packed f32x2 helpers (attention FFMA2 path) ----
__device__ __forceinline__ u64 pack2(float lo, float hi) {
    u64 r; asm("mov.b64 %0, {%1, %2};" : "=l"(r) : "f"(lo), "f"(hi)); return r;
}
__device__ __forceinline__ void unpack2(u64 v, float& lo, float& hi) {
    asm("mov.b64 {%0, %1}, %2;" : "=f"(lo), "=f"(hi) : "l"(v));
}
__device__ __forceinline__ void ffma2(u64& d, u64 a, u64 b) {
    asm("fma.rn.f32x2 %0, %1, %2, %0;" : "+l"(d) : "l"(a), "l"(b));
}
__device__ __forceinline__ u64 mul2(u64 a, u64 b) {
    u64 d; asm("mul.rn.f32x2 %0, %1, %2;" : "=l"(d) : "l"(a), "l"(b)); return d;
}

// ---- warp-level bf16 MMA (sm_80+, works at compute_100) ----
__device__ __forceinline__ void mma_bf16(float* c, const uint32_t* a, const uint32_t* b) {
    asm("mma.sync.aligned.m16n8k16.row.col.f32.bf16.bf16.f32 "
        "{%0,%1,%2,%3}, {%4,%5,%6,%7}, {%8,%9}, {%0,%1,%2,%3};"
        : "+f"(c[0]), "+f"(c[1]), "+f"(c[2]), "+f"(c[3])
        : "r"(a[0]), "r"(a[1]), "r"(a[2]), "r"(a[3]), "r"(b[0]), "r"(b[1]));
}

// Scratch (device globals: allocation-free contract)
__device__ float g_kvlat[(size_t)ROWS * DLAT];
__device__ float g_qlat [(size_t)ROWS * DLAT];
__device__ float g_kvfull[(size_t)ROWS * KVFD];
__device__ float g_qfull [(size_t)ROWS * QFD];
__device__ float g_ctx   [(size_t)ROWS * DMODEL];
// Weight planes: transposed [N][K], split into bf16 hi/lo
__device__ unsigned short g_wkvd_h[(size_t)DLAT * DMODEL], g_wkvd_l[(size_t)DLAT * DMODEL];
__device__ unsigned short g_wqd_h [(size_t)DLAT * DMODEL], g_wqd_l [(size_t)DLAT * DMODEL];
__device__ unsigned short g_wkvu_h[(size_t)KVFD * DLAT],   g_wkvu_l[(size_t)KVFD * DLAT];
__device__ unsigned short g_wqu_h [(size_t)QFD  * DLAT],   g_wqu_l [(size_t)QFD  * DLAT];
__device__ unsigned short g_wo_h  [(size_t)DMODEL*DMODEL], g_wo_l  [(size_t)DMODEL*DMODEL];

// ---------------------------------------------------------------------------
// Transpose + bf16 split: in [R][C] fp32 -> out_hi/out_lo [C][R] bf16.
// hi = top-16-bit truncation (v - hi is EXACT), lo = top-16 of residual.
// ---------------------------------------------------------------------------
__global__ __launch_bounds__(256) void transpose_split_kernel(
    const float* __restrict__ in, unsigned short* __restrict__ oh,
    unsigned short* __restrict__ ol, int R, int C)
{
    __shared__ float tile[32][33];
    int c0 = blockIdx.x * 32, r0 = blockIdx.y * 32;
    int tx = threadIdx.x, ty = threadIdx.y;
#pragma unroll
    for (int i = ty; i < 32; i += 8)
        tile[i][tx] = in[(size_t)(r0 + i) * C + c0 + tx];
    __syncthreads();
#pragma unroll
    for (int i = ty; i < 32; i += 8) {
        float v = tile[tx][i];
        uint32_t b = __float_as_uint(v);
        float res = v - __uint_as_float(b & 0xFFFF0000u);
        size_t o = (size_t)(c0 + i) * R + r0 + tx;
        oh[o] = (unsigned short)(b >> 16);
        ol[o] = (unsigned short)(__float_as_uint(res) >> 16);
    }
}

// ---------------------------------------------------------------------------
// HMMA split-bf16 GEMM: C[M,N] = A[M,K] (fp32) @ Bt[N,K]^T (bf16 hi/lo planes).
// 128x128 tile, 256 thr, 8 warps (2x4), warp tile 64x32, K-chunk 16,
// double-buffered 48KB static smem. 3 mmas per k16 subtile (hh + hl + lh).
// Plane row stride 12 words -> all fragment LDS are bank-conflict free.
// ---------------------------------------------------------------------------
#define PSTR 12                // words per 16-bf16 plane row (incl. pad)
#define PLW  (128 * PSTR)      // words per plane
#define STW  (4 * PLW)         // words per stage (Ah, Al, Bh, Bl)

__global__ __launch_bounds__(256) void hmma_gemm(
    const float* __restrict__ A, const unsigned short* __restrict__ Bh,
    const unsigned short* __restrict__ Bl, float* __restrict__ C,
    int M, int N, int K)
{
    __shared__ __align__(16) uint32_t smw[2 * STW];   // 48 KB

    const int tid  = threadIdx.x;
    const int lane = tid & 31, wid = tid >> 5;
    const int g = lane >> 2, t = lane & 3;
    const int wm = wid >> 2, wn = wid & 3;            // 2 x 4 warp grid
    const int bx = blockIdx.x, by = blockIdx.y;

    const float* Ab = A + (size_t)by * 128 * K;
    const unsigned short* Bhb = Bh + (size_t)bx * 128 * K;
    const unsigned short* Blb = Bl + (size_t)bx * 128 * K;

    float acc[4][4][4];
#pragma unroll
    for (int mt = 0; mt < 4; mt++)
#pragma unroll
        for (int nt = 0; nt < 4; nt++)
#pragma unroll
            for (int q = 0; q < 4; q++) acc[mt][nt][q] = 0.f;

    // staging index maps
    const int ar = tid >> 2, ac4 = tid & 3;   // A: rows ar, ar+64; 4-float chunk ac4
    const int br = tid >> 1, bh2 = tid & 1;   // B: row br; 8-elem half bh2

    float4 av[2]; uint4 bhv, blv;

    // ---- prologue: global load + split + store stage 0 ----
    av[0] = *(const float4*)&Ab[(size_t)ar * K + ac4 * 4];
    av[1] = *(const float4*)&Ab[(size_t)(ar + 64) * K + ac4 * 4];
    bhv = *(const uint4*)&Bhb[(size_t)br * K + bh2 * 8];
    blv = *(const uint4*)&Blb[(size_t)br * K + bh2 * 8];
    {
        uint32_t* Ah = smw;  uint32_t* Al = Ah + PLW;
        uint32_t* Bhs = Al + PLW; uint32_t* Bls = Bhs + PLW;
#pragma unroll
        for (int i = 0; i < 2; i++) {
            float4 v = av[i];
            uint32_t xb = __float_as_uint(v.x), yb = __float_as_uint(v.y);
            uint32_t zb = __float_as_uint(v.z), wb = __float_as_uint(v.w);
            float rx = v.x - __uint_as_float(xb & 0xFFFF0000u);
            float ry = v.y - __uint_as_float(yb & 0xFFFF0000u);
            float rz = v.z - __uint_as_float(zb & 0xFFFF0000u);
            float rw = v.w - __uint_as_float(wb & 0xFFFF0000u);
            int base = (ar + 64 * i) * PSTR + ac4 * 2;
            Ah[base]     = __byte_perm(xb, yb, 0x7632);
            Ah[base + 1] = __byte_perm(zb, wb, 0x7632);
            Al[base]     = __byte_perm(__float_as_uint(rx), __float_as_uint(ry), 0x7632);
            Al[base + 1] = __byte_perm(__float_as_uint(rz), __float_as_uint(rw), 0x7632);
        }
        int bb = br * PSTR + bh2 * 4;
        *(uint4*)&Bhs[bb] = bhv;
        *(uint4*)&Bls[bb] = blv;
    }
    __syncthreads();

    const int NS = K / 16;
    for (int sI = 0; sI < NS; sI++) {
        const int cur = sI & 1;
        const bool more = (sI + 1) < NS;
        if (more) {
            const int k0 = (sI + 1) * 16;
            av[0] = *(const float4*)&Ab[(size_t)ar * K + k0 + ac4 * 4];
            av[1] = *(const float4*)&Ab[(size_t)(ar + 64) * K + k0 + ac4 * 4];
            bhv = *(const uint4*)&Bhb[(size_t)br * K + k0 + bh2 * 8];
            blv = *(const uint4*)&Blb[(size_t)br * K + k0 + bh2 * 8];
        }

        // ---- compute on stage cur ----
        {
            const uint32_t* Ah = smw + cur * STW;
            const uint32_t* Al = Ah + PLW;
            const uint32_t* Bhs = Al + PLW;
            const uint32_t* Bls = Bhs + PLW;

            uint32_t bfh[4][2], bfl[4][2];
#pragma unroll
            for (int nt = 0; nt < 4; nt++) {
                int nr = (wn * 32 + nt * 8 + g) * PSTR + t;
                bfh[nt][0] = Bhs[nr];     bfh[nt][1] = Bhs[nr + 4];
                bfl[nt][0] = Bls[nr];     bfl[nt][1] = Bls[nr + 4];
            }
#pragma unroll
            for (int mt = 0; mt < 4; mt++) {
                int r0 = (wm * 64 + mt * 16 + g) * PSTR + t;
                int r8 = r0 + 8 * PSTR;
                uint32_t ah[4], al[4];
                ah[0] = Ah[r0]; ah[1] = Ah[r8]; ah[2] = Ah[r0 + 4]; ah[3] = Ah[r8 + 4];
                al[0] = Al[r0]; al[1] = Al[r8]; al[2] = Al[r0 + 4]; al[3] = Al[r8 + 4];
#pragma unroll
                for (int nt = 0; nt < 4; nt++) {
                    mma_bf16(acc[mt][nt], ah, bfh[nt]);   // hi*hi
                    mma_bf16(acc[mt][nt], ah, bfl[nt]);   // hi*lo
                    mma_bf16(acc[mt][nt], al, bfh[nt]);   // lo*hi
                }
            }
        }

        if (more) {
            uint32_t* Ah = smw + (cur ^ 1) * STW;
            uint32_t* Al = Ah + PLW;
            uint32_t* Bhs = Al + PLW;
            uint32_t* Bls = Bhs + PLW;
#pragma unroll
            for (int i = 0; i < 2; i++) {
                float4 v = av[i];
                uint32_t xb = __float_as_uint(v.x), yb = __float_as_uint(v.y);
                uint32_t zb = __float_as_uint(v.z), wb = __float_as_uint(v.w);
                float rx = v.x - __uint_as_float(xb & 0xFFFF0000u);
                float ry = v.y - __uint_as_float(yb & 0xFFFF0000u);
                float rz = v.z - __uint_as_float(zb & 0xFFFF0000u);
                float rw = v.w - __uint_as_float(wb & 0xFFFF0000u);
                int base = (ar + 64 * i) * PSTR + ac4 * 2;
                Ah[base]     = __byte_perm(xb, yb, 0x7632);
                Ah[base + 1] = __byte_perm(zb, wb, 0x7632);
                Al[base]     = __byte_perm(__float_as_uint(rx), __float_as_uint(ry), 0x7632);
                Al[base + 1] = __byte_perm(__float_as_uint(rz), __float_as_uint(rw), 0x7632);
            }
            int bb = br * PSTR + bh2 * 4;
            *(uint4*)&Bhs[bb] = bhv;
            *(uint4*)&Bls[bb] = blv;
        }
        __syncthreads();
    }

    // ---- epilogue ----
#pragma unroll
    for (int mt = 0; mt < 4; mt++) {
        int row = by * 128 + wm * 64 + mt * 16 + g;
#pragma unroll
        for (int nt = 0; nt < 4; nt++) {
            int col = bx * 128 + wn * 32 + nt * 8 + 2 * t;
            *(float2*)&C[(size_t)row * N + col]       = make_float2(acc[mt][nt][0], acc[mt][nt][1]);
            *(float2*)&C[(size_t)(row + 8) * N + col] = make_float2(acc[mt][nt][2], acc[mt][nt][3]);
        }
    }
}

// ---------------------------------------------------------------------------
// RoPE (in-place on q_full and kv_full rope slices).
// ---------------------------------------------------------------------------
__global__ __launch_bounds__(512) void rope_kernel()
{
    const int row = blockIdx.x;         // b*S + s
    const int s   = row & (S_ - 1);
    const int h   = threadIdx.x >> 5;
    const int j   = threadIdx.x & 31;

    const float inv = expf(-(float)j * (9.210340371976184f / 32.f));
    const float f   = (float)s * inv;
    const float c   = cosf(f);
    const float sn  = sinf(f);

    {
        size_t base = (size_t)row * QFD + h * DQK + DH;
        float x1 = g_qfull[base + j];
        float x2 = g_qfull[base + 32 + j];
        g_qfull[base + j]      = x1 * c - x2 * sn;
        g_qfull[base + 32 + j] = x2 * c + x1 * sn;
    }
    {
        size_t base = (size_t)row * KVFD + h * KVD + DH;
        float x1 = g_kvfull[base + j];
        float x2 = g_kvfull[base + 32 + j];
        g_kvfull[base + j]      = x1 * c - x2 * sn;
        g_kvfull[base + 32 + j] = x2 * c + x1 * sn;
    }
}

// ---------------------------------------------------------------------------
// Flash attention (causal): BM=128, BN=64, 256 threads, FFMA2. (unchanged)
// ---------------------------------------------------------------------------
#define ABM 128
#define ABN 64
#define KSTR 196               // 192 padded (Q/K row stride)
#define VSTR 128
#define SSTR 68                // 64 padded
#define ATTN_SMEM_FLOATS (ABM*KSTR + ABN*KSTR + ABN*VSTR + ABM*SSTR)
#define ATTN_SMEM_BYTES  (ATTN_SMEM_FLOATS * 4)

__global__ __launch_bounds__(256, 1) void attn_kernel()
{
    extern __shared__ float sm[];
    float* Qs = sm;                    // [128][196]
    float* Ks = Qs + ABM * KSTR;       // [64][196]
    float* Vs = Ks + ABN * KSTR;       // [64][128]
    float* Ss = Vs + ABN * VSTR;       // [128][68]

    const int qt  = gridDim.x - 1 - blockIdx.x;   // long blocks first
    const int h   = blockIdx.y;
    const int b   = blockIdx.z;
    const int tid = threadIdx.x;
    const int ry  = tid >> 4;          // 0..15
    const int cx  = tid & 15;          // 0..15
    const int qs0 = qt * ABM;

    const float scale = 0.07216878364870323f;     // 1/sqrt(192)

    int rows[8];
#pragma unroll
    for (int i = 0; i < 8; i++)
        rows[i] = (i < 4) ? (ry * 4 + i) : (64 + ry * 4 + (i - 4));

    // Load Q tile (scaled)
    for (int f = tid; f < ABM * 48; f += 256) {
        int r = f / 48, d4 = f % 48;
        float4 q = *(const float4*)&g_qfull[(size_t)(b * S_ + qs0 + r) * QFD + h * DQK + d4 * 4];
        q.x *= scale; q.y *= scale; q.z *= scale; q.w *= scale;
        *(float4*)&Qs[r * KSTR + d4 * 4] = q;
    }

    float m_run[8], l_run[8];
    u64 o2[8][4];
#pragma unroll
    for (int i = 0; i < 8; i++) {
        m_run[i] = -1e30f; l_run[i] = 0.f;
#pragma unroll
        for (int t = 0; t < 4; t++) o2[i][t] = 0ull;
    }

    __syncthreads();

    for (int kt = 0; kt <= qs0 + 64; kt += ABN) {
        // Load K (192 dims) + V (128 dims) for 64 key rows
        for (int f = tid; f < ABN * 80; f += 256) {
            int r = f / 80, v = f % 80;
            float4 t = *(const float4*)&g_kvfull[(size_t)(b * S_ + kt + r) * KVFD + h * KVD + v * 4];
            if (v < 48) *(float4*)&Ks[r * KSTR + v * 4] = t;
            else        *(float4*)&Vs[r * VSTR + (v - 48) * 4] = t;
        }
        __syncthreads();

        // ---- scores: 8x4 per thread, packed along k (even/odd lanes) ----
        u64 s2[8][4];
#pragma unroll
        for (int i = 0; i < 8; i++)
#pragma unroll
            for (int j = 0; j < 4; j++) s2[i][j] = 0ull;

#pragma unroll 2
        for (int k = 0; k < DQK; k += 4) {
            ulonglong2 kv2[4];
#pragma unroll
            for (int j = 0; j < 4; j++)
                kv2[j] = *(const ulonglong2*)&Ks[(cx + 16 * j) * KSTR + k];
#pragma unroll
            for (int i = 0; i < 8; i++) {
                ulonglong2 qv2 = *(const ulonglong2*)&Qs[rows[i] * KSTR + k];
#pragma unroll
                for (int j = 0; j < 4; j++) {
                    ffma2(s2[i][j], qv2.x, kv2[j].x);
                    ffma2(s2[i][j], qv2.y, kv2[j].y);
                }
            }
        }

        float s[8][4];
#pragma unroll
        for (int i = 0; i < 8; i++)
#pragma unroll
            for (int j = 0; j < 4; j++) {
                float lo, hi; unpack2(s2[i][j], lo, hi);
                s[i][j] = lo + hi;
            }

        // causal mask (only the two diagonal-straddling tiles)
        if (kt >= qs0) {
#pragma unroll
            for (int i = 0; i < 8; i++)
#pragma unroll
                for (int j = 0; j < 4; j++)
                    if (kt + cx + 16 * j > qs0 + rows[i]) s[i][j] = -1e30f;
        }

        // ---- online softmax (per-row state in registers) ----
#pragma unroll
        for (int i = 0; i < 8; i++) {
            float rm = fmaxf(fmaxf(s[i][0], s[i][1]), fmaxf(s[i][2], s[i][3]));
            rm = fmaxf(rm, __shfl_xor_sync(0xffffffffu, rm, 1));
            rm = fmaxf(rm, __shfl_xor_sync(0xffffffffu, rm, 2));
            rm = fmaxf(rm, __shfl_xor_sync(0xffffffffu, rm, 4));
            rm = fmaxf(rm, __shfl_xor_sync(0xffffffffu, rm, 8));
            float m_new = fmaxf(m_run[i], rm);
            float p0 = __expf(s[i][0] - m_new);
            float p1 = __expf(s[i][1] - m_new);
            float p2 = __expf(s[i][2] - m_new);
            float p3 = __expf(s[i][3] - m_new);
            float rs = p0 + p1 + p2 + p3;
            rs += __shfl_xor_sync(0xffffffffu, rs, 1);
            rs += __shfl_xor_sync(0xffffffffu, rs, 2);
            rs += __shfl_xor_sync(0xffffffffu, rs, 4);
            rs += __shfl_xor_sync(0xffffffffu, rs, 8);
            float corr = __expf(m_run[i] - m_new);
            l_run[i] = l_run[i] * corr + rs;
            m_run[i] = m_new;
            u64 c2 = pack2(corr, corr);
#pragma unroll
            for (int t = 0; t < 4; t++) o2[i][t] = mul2(o2[i][t], c2);
            Ss[rows[i] * SSTR + cx]      = p0;
            Ss[rows[i] * SSTR + cx + 16] = p1;
            Ss[rows[i] * SSTR + cx + 32] = p2;
            Ss[rows[i] * SSTR + cx + 48] = p3;
        }
        __syncthreads();

        // ---- PV: 8 rows x 8 cols per thread, cols packed as f32x2 ----
#pragma unroll 2
        for (int j4 = 0; j4 < 16; j4++) {
            float4 pv[8];
#pragma unroll
            for (int i = 0; i < 8; i++)
                pv[i] = *(const float4*)&Ss[rows[i] * SSTR + j4 * 4];
#pragma unroll
            for (int jj = 0; jj < 4; jj++) {
                ulonglong2 v0 = *(const ulonglong2*)&Vs[(j4 * 4 + jj) * VSTR + cx * 4];
                ulonglong2 v1 = *(const ulonglong2*)&Vs[(j4 * 4 + jj) * VSTR + 64 + cx * 4];
#pragma unroll
                for (int i = 0; i < 8; i++) {
                    float p = (jj == 0) ? pv[i].x : (jj == 1) ? pv[i].y
                            : (jj == 2) ? pv[i].z : pv[i].w;
                    u64 pd = pack2(p, p);
                    ffma2(o2[i][0], pd, v0.x);
                    ffma2(o2[i][1], pd, v0.y);
                    ffma2(o2[i][2], pd, v1.x);
                    ffma2(o2[i][3], pd, v1.y);
                }
            }
        }
        __syncthreads();   // protect Ks/Vs/Ss before next tile load
    }

    // Finalize and store context (layout [b,s,h*128+d])
#pragma unroll
    for (int i = 0; i < 8; i++) {
        float inv_l = 1.f / l_run[i];
        float4 c0, c1;
        unpack2(o2[i][0], c0.x, c0.y);
        unpack2(o2[i][1], c0.z, c0.w);
        unpack2(o2[i][2], c1.x, c1.y);
        unpack2(o2[i][3], c1.z, c1.w);
        c0.x *= inv_l; c0.y *= inv_l; c0.z *= inv_l; c0.w *= inv_l;
        c1.x *= inv_l; c1.y *= inv_l; c1.z *= inv_l; c1.w *= inv_l;
        size_t base = (size_t)(b * S_ + qs0 + rows[i]) * DMODEL + h * DH;
        *(float4*)&g_ctx[base + cx * 4]      = c0;
        *(float4*)&g_ctx[base + 64 + cx * 4] = c1;
    }
}

// ---------------------------------------------------------------------------
// Launch
// ---------------------------------------------------------------------------
extern "C" void kernel_launch(void* const* d_in, const int* in_sizes, int n_in,
                              void* d_out, int out_size)
{
    (void)in_sizes; (void)n_in; (void)out_size;
    const float* x    = (const float*)d_in[0];
    const float* Wkvd = (const float*)d_in[1];
    const float* Wkvu = (const float*)d_in[2];
    const float* Wqd  = (const float*)d_in[3];
    const float* Wqu  = (const float*)d_in[4];
    const float* Wo   = (const float*)d_in[5];
    float* out = (float*)d_out;

    float *kvlat, *qlat, *kvfull, *qfull, *ctx;
    unsigned short *wkvdH, *wkvdL, *wqdH, *wqdL, *wkvuH, *wkvuL, *wquH, *wquL, *woH, *woL;
    cudaGetSymbolAddress((void**)&kvlat,  g_kvlat);
    cudaGetSymbolAddress((void**)&qlat,   g_qlat);
    cudaGetSymbolAddress((void**)&kvfull, g_kvfull);
    cudaGetSymbolAddress((void**)&qfull,  g_qfull);
    cudaGetSymbolAddress((void**)&ctx,    g_ctx);
    cudaGetSymbolAddress((void**)&wkvdH,  g_wkvd_h);
    cudaGetSymbolAddress((void**)&wkvdL,  g_wkvd_l);
    cudaGetSymbolAddress((void**)&wqdH,   g_wqd_h);
    cudaGetSymbolAddress((void**)&wqdL,   g_wqd_l);
    cudaGetSymbolAddress((void**)&wkvuH,  g_wkvu_h);
    cudaGetSymbolAddress((void**)&wkvuL,  g_wkvu_l);
    cudaGetSymbolAddress((void**)&wquH,   g_wqu_h);
    cudaGetSymbolAddress((void**)&wquL,   g_wqu_l);
    cudaGetSymbolAddress((void**)&woH,    g_wo_h);
    cudaGetSymbolAddress((void**)&woL,    g_wo_l);

    dim3 tt(32, 8);
    // 0) transpose + split weights to bf16 hi/lo planes [N][K]
    transpose_split_kernel<<<dim3(DLAT / 32, DMODEL / 32), tt>>>(Wkvd, wkvdH, wkvdL, DMODEL, DLAT);
    transpose_split_kernel<<<dim3(DLAT / 32, DMODEL / 32), tt>>>(Wqd,  wqdH,  wqdL,  DMODEL, DLAT);
    transpose_split_kernel<<<dim3(KVFD / 32, DLAT / 32),   tt>>>(Wkvu, wkvuH, wkvuL, DLAT,  KVFD);
    transpose_split_kernel<<<dim3(QFD  / 32, DLAT / 32),   tt>>>(Wqu,  wquH,  wquL,  DLAT,  QFD);
    transpose_split_kernel<<<dim3(DMODEL / 32, DMODEL / 32), tt>>>(Wo, woH,   woL,   DMODEL, DMODEL);

    dim3 t(256);
    // 1) down-projections
    hmma_gemm<<<dim3(DLAT / 128, ROWS / 128), t>>>(x, wkvdH, wkvdL, kvlat, ROWS, DLAT, DMODEL);
    hmma_gemm<<<dim3(DLAT / 128, ROWS / 128), t>>>(x, wqdH,  wqdL,  qlat,  ROWS, DLAT, DMODEL);
    // 2) up-projections
    hmma_gemm<<<dim3(KVFD / 128, ROWS / 128), t>>>(kvlat, wkvuH, wkvuL, kvfull, ROWS, KVFD, DLAT);
    hmma_gemm<<<dim3(QFD  / 128, ROWS / 128), t>>>(qlat,  wquH,  wquL,  qfull,  ROWS, QFD,  DLAT);
    // 3) RoPE in place
    rope_kernel<<<ROWS, 512>>>();
    // 4) attention
    cudaFuncSetAttribute(attn_kernel, cudaFuncAttributeMaxDynamicSharedMemorySize, ATTN_SMEM_BYTES);
    attn_kernel<<<dim3(S_ / ABM, NH, B_), 256, ATTN_SMEM_BYTES>>>();
    // 5) output projection
    hmma_gemm<<<dim3(DMODEL / 128, ROWS / 128), t>>>(ctx, woH, woL, out, ROWS, DMODEL, DMODEL);
}

// round 9
// speedup vs baseline: 2.8510x; 1.3141x over previous
#include <cuda_runtime.h>
#include <cuda_bf16.h>
#include <math.h>
#include <stdint.h>

// Problem constants
#define B_      2
#define S_      2048
#define DMODEL  2048
#define NH      16
#define DH      128
#define DLAT    512
#define DR      64
#define DQK     192            // DH + DR
#define KVD     320            // DH + DR + DH
#define QFD     3072           // NH * DQK
#define KVFD    5120           // NH * KVD
#define ROWS    (B_*S_)        // 4096

// ---- warp-level bf16 MMA (sm_80+, works at compute_100) ----
__device__ __forceinline__ void mma_bf16(float* c, const uint32_t* a, const uint32_t* b) {
    asm("mma.sync.aligned.m16n8k16.row.col.f32.bf16.bf16.f32 "
        "{%0,%1,%2,%3}, {%4,%5,%6,%7}, {%8,%9}, {%0,%1,%2,%3};"
        : "+f"(c[0]), "+f"(c[1]), "+f"(c[2]), "+f"(c[3])
        : "r"(a[0]), "r"(a[1]), "r"(a[2]), "r"(a[3]), "r"(b[0]), "r"(b[1]));
}
__device__ __forceinline__ void ldsm4(uint32_t* r, uint32_t a) {
    asm volatile("ldmatrix.sync.aligned.m8n8.x4.shared.b16 {%0,%1,%2,%3}, [%4];"
        : "=r"(r[0]), "=r"(r[1]), "=r"(r[2]), "=r"(r[3]) : "r"(a));
}

// Scratch (device globals: allocation-free contract)
__device__ float g_kvlat[(size_t)ROWS * DLAT];
__device__ float g_qlat [(size_t)ROWS * DLAT];
__device__ float g_kvfull[(size_t)ROWS * KVFD];
__device__ float g_qfull [(size_t)ROWS * QFD];
__device__ float g_ctx   [(size_t)ROWS * DMODEL];
// Weight planes: transposed [N][K], split into bf16 hi/lo
__device__ unsigned short g_wkvd_h[(size_t)DLAT * DMODEL], g_wkvd_l[(size_t)DLAT * DMODEL];
__device__ unsigned short g_wqd_h [(size_t)DLAT * DMODEL], g_wqd_l [(size_t)DLAT * DMODEL];
__device__ unsigned short g_wkvu_h[(size_t)KVFD * DLAT],   g_wkvu_l[(size_t)KVFD * DLAT];
__device__ unsigned short g_wqu_h [(size_t)QFD  * DLAT],   g_wqu_l [(size_t)QFD  * DLAT];
__device__ unsigned short g_wo_h  [(size_t)DMODEL*DMODEL], g_wo_l  [(size_t)DMODEL*DMODEL];
// Attention operand planes (bf16 hi/lo), post-rope
__device__ unsigned short g_qh [(size_t)ROWS * (NH*DQK)], g_ql [(size_t)ROWS * (NH*DQK)];
__device__ unsigned short g_kh [(size_t)ROWS * (NH*DQK)], g_kl [(size_t)ROWS * (NH*DQK)];
__device__ unsigned short g_vth[(size_t)B_*NH*DH * S_],   g_vtl[(size_t)B_*NH*DH * S_];

// ---------------------------------------------------------------------------
// Transpose + bf16 split (weights): in [R][C] fp32 -> hi/lo [C][R] bf16.
// ---------------------------------------------------------------------------
__global__ __launch_bounds__(256) void transpose_split_kernel(
    const float* __restrict__ in, unsigned short* __restrict__ oh,
    unsigned short* __restrict__ ol, int R, int C)
{
    __shared__ float tile[32][33];
    int c0 = blockIdx.x * 32, r0 = blockIdx.y * 32;
    int tx = threadIdx.x, ty = threadIdx.y;
#pragma unroll
    for (int i = ty; i < 32; i += 8)
        tile[i][tx] = in[(size_t)(r0 + i) * C + c0 + tx];
    __syncthreads();
#pragma unroll
    for (int i = ty; i < 32; i += 8) {
        float v = tile[tx][i];
        uint32_t b = __float_as_uint(v);
        float res = v - __uint_as_float(b & 0xFFFF0000u);
        size_t o = (size_t)(c0 + i) * R + r0 + tx;
        oh[o] = (unsigned short)(b >> 16);
        ol[o] = (unsigned short)(__float_as_uint(res) >> 16);
    }
}

// ---------------------------------------------------------------------------
// HMMA split-bf16 GEMM (unchanged from round 8).
// ---------------------------------------------------------------------------
#define PSTR 12
#define PLW  (128 * PSTR)
#define STW  (4 * PLW)

__global__ __launch_bounds__(256) void hmma_gemm(
    const float* __restrict__ A, const unsigned short* __restrict__ Bh,
    const unsigned short* __restrict__ Bl, float* __restrict__ C,
    int M, int N, int K)
{
    __shared__ __align__(16) uint32_t smw[2 * STW];

    const int tid  = threadIdx.x;
    const int lane = tid & 31, wid = tid >> 5;
    const int g = lane >> 2, t = lane & 3;
    const int wm = wid >> 2, wn = wid & 3;
    const int bx = blockIdx.x, by = blockIdx.y;

    const float* Ab = A + (size_t)by * 128 * K;
    const unsigned short* Bhb = Bh + (size_t)bx * 128 * K;
    const unsigned short* Blb = Bl + (size_t)bx * 128 * K;

    float acc[4][4][4];
#pragma unroll
    for (int mt = 0; mt < 4; mt++)
#pragma unroll
        for (int nt = 0; nt < 4; nt++)
#pragma unroll
            for (int q = 0; q < 4; q++) acc[mt][nt][q] = 0.f;

    const int ar = tid >> 2, ac4 = tid & 3;
    const int br = tid >> 1, bh2 = tid & 1;

    float4 av[2]; uint4 bhv, blv;

    av[0] = *(const float4*)&Ab[(size_t)ar * K + ac4 * 4];
    av[1] = *(const float4*)&Ab[(size_t)(ar + 64) * K + ac4 * 4];
    bhv = *(const uint4*)&Bhb[(size_t)br * K + bh2 * 8];
    blv = *(const uint4*)&Blb[(size_t)br * K + bh2 * 8];
    {
        uint32_t* Ah = smw;  uint32_t* Al = Ah + PLW;
        uint32_t* Bhs = Al + PLW; uint32_t* Bls = Bhs + PLW;
#pragma unroll
        for (int i = 0; i < 2; i++) {
            float4 v = av[i];
            uint32_t xb = __float_as_uint(v.x), yb = __float_as_uint(v.y);
            uint32_t zb = __float_as_uint(v.z), wb = __float_as_uint(v.w);
            float rx = v.x - __uint_as_float(xb & 0xFFFF0000u);
            float ry = v.y - __uint_as_float(yb & 0xFFFF0000u);
            float rz = v.z - __uint_as_float(zb & 0xFFFF0000u);
            float rw = v.w - __uint_as_float(wb & 0xFFFF0000u);
            int base = (ar + 64 * i) * PSTR + ac4 * 2;
            Ah[base]     = __byte_perm(xb, yb, 0x7632);
            Ah[base + 1] = __byte_perm(zb, wb, 0x7632);
            Al[base]     = __byte_perm(__float_as_uint(rx), __float_as_uint(ry), 0x7632);
            Al[base + 1] = __byte_perm(__float_as_uint(rz), __float_as_uint(rw), 0x7632);
        }
        int bb = br * PSTR + bh2 * 4;
        *(uint4*)&Bhs[bb] = bhv;
        *(uint4*)&Bls[bb] = blv;
    }
    __syncthreads();

    const int NS = K / 16;
    for (int sI = 0; sI < NS; sI++) {
        const int cur = sI & 1;
        const bool more = (sI + 1) < NS;
        if (more) {
            const int k0 = (sI + 1) * 16;
            av[0] = *(const float4*)&Ab[(size_t)ar * K + k0 + ac4 * 4];
            av[1] = *(const float4*)&Ab[(size_t)(ar + 64) * K + k0 + ac4 * 4];
            bhv = *(const uint4*)&Bhb[(size_t)br * K + k0 + bh2 * 8];
            blv = *(const uint4*)&Blb[(size_t)br * K + k0 + bh2 * 8];
        }
        {
            const uint32_t* Ah = smw + cur * STW;
            const uint32_t* Al = Ah + PLW;
            const uint32_t* Bhs = Al + PLW;
            const uint32_t* Bls = Bhs + PLW;

            uint32_t bfh[4][2], bfl[4][2];
#pragma unroll
            for (int nt = 0; nt < 4; nt++) {
                int nr = (wn * 32 + nt * 8 + g) * PSTR + t;
                bfh[nt][0] = Bhs[nr];     bfh[nt][1] = Bhs[nr + 4];
                bfl[nt][0] = Bls[nr];     bfl[nt][1] = Bls[nr + 4];
            }
#pragma unroll
            for (int mt = 0; mt < 4; mt++) {
                int r0 = (wm * 64 + mt * 16 + g) * PSTR + t;
                int r8 = r0 + 8 * PSTR;
                uint32_t ah[4], al[4];
                ah[0] = Ah[r0]; ah[1] = Ah[r8]; ah[2] = Ah[r0 + 4]; ah[3] = Ah[r8 + 4];
                al[0] = Al[r0]; al[1] = Al[r8]; al[2] = Al[r0 + 4]; al[3] = Al[r8 + 4];
#pragma unroll
                for (int nt = 0; nt < 4; nt++) {
                    mma_bf16(acc[mt][nt], ah, bfh[nt]);
                    mma_bf16(acc[mt][nt], ah, bfl[nt]);
                    mma_bf16(acc[mt][nt], al, bfh[nt]);
                }
            }
        }
        if (more) {
            uint32_t* Ah = smw + (cur ^ 1) * STW;
            uint32_t* Al = Ah + PLW;
            uint32_t* Bhs = Al + PLW;
            uint32_t* Bls = Bhs + PLW;
#pragma unroll
            for (int i = 0; i < 2; i++) {
                float4 v = av[i];
                uint32_t xb = __float_as_uint(v.x), yb = __float_as_uint(v.y);
                uint32_t zb = __float_as_uint(v.z), wb = __float_as_uint(v.w);
                float rx = v.x - __uint_as_float(xb & 0xFFFF0000u);
                float ry = v.y - __uint_as_float(yb & 0xFFFF0000u);
                float rz = v.z - __uint_as_float(zb & 0xFFFF0000u);
                float rw = v.w - __uint_as_float(wb & 0xFFFF0000u);
                int base = (ar + 64 * i) * PSTR + ac4 * 2;
                Ah[base]     = __byte_perm(xb, yb, 0x7632);
                Ah[base + 1] = __byte_perm(zb, wb, 0x7632);
                Al[base]     = __byte_perm(__float_as_uint(rx), __float_as_uint(ry), 0x7632);
                Al[base + 1] = __byte_perm(__float_as_uint(rz), __float_as_uint(rw), 0x7632);
            }
            int bb = br * PSTR + bh2 * 4;
            *(uint4*)&Bhs[bb] = bhv;
            *(uint4*)&Bls[bb] = blv;
        }
        __syncthreads();
    }

#pragma unroll
    for (int mt = 0; mt < 4; mt++) {
        int row = by * 128 + wm * 64 + mt * 16 + g;
#pragma unroll
        for (int nt = 0; nt < 4; nt++) {
            int col = bx * 128 + wn * 32 + nt * 8 + 2 * t;
            *(float2*)&C[(size_t)row * N + col]       = make_float2(acc[mt][nt][0], acc[mt][nt][1]);
            *(float2*)&C[(size_t)(row + 8) * N + col] = make_float2(acc[mt][nt][2], acc[mt][nt][3]);
        }
    }
}

// ---------------------------------------------------------------------------
// RoPE (in-place on q_full and kv_full rope slices).
// ---------------------------------------------------------------------------
__global__ __launch_bounds__(512) void rope_kernel()
{
    const int row = blockIdx.x;
    const int s   = row & (S_ - 1);
    const int h   = threadIdx.x >> 5;
    const int j   = threadIdx.x & 31;

    const float inv = expf(-(float)j * (9.210340371976184f / 32.f));
    const float f   = (float)s * inv;
    const float c   = cosf(f);
    const float sn  = sinf(f);

    {
        size_t base = (size_t)row * QFD + h * DQK + DH;
        float x1 = g_qfull[base + j];
        float x2 = g_qfull[base + 32 + j];
        g_qfull[base + j]      = x1 * c - x2 * sn;
        g_qfull[base + 32 + j] = x2 * c + x1 * sn;
    }
    {
        size_t base = (size_t)row * KVFD + h * KVD + DH;
        float x1 = g_kvfull[base + j];
        float x2 = g_kvfull[base + 32 + j];
        g_kvfull[base + j]      = x1 * c - x2 * sn;
        g_kvfull[base + 32 + j] = x2 * c + x1 * sn;
    }
}

// ---------------------------------------------------------------------------
// Split helpers: fp32 -> bf16 hi/lo words
// ---------------------------------------------------------------------------
__device__ __forceinline__ void split_pair(float a, float b, uint32_t& hw, uint32_t& lw) {
    uint32_t ua = __float_as_uint(a), ub = __float_as_uint(b);
    float ra = a - __uint_as_float(ua & 0xFFFF0000u);
    float rb = b - __uint_as_float(ub & 0xFFFF0000u);
    hw = __byte_perm(ua, ub, 0x7632);
    lw = __byte_perm(__float_as_uint(ra), __float_as_uint(rb), 0x7632);
}

// Q split (scale folded): g_qfull -> g_qh/g_ql, same layout
__global__ __launch_bounds__(256) void qsplit_kernel()
{
    const float scale = 0.07216878364870323f;   // 1/sqrt(192)
    size_t f = (size_t)blockIdx.x * 256 + threadIdx.x;   // float4 index
    float4 v = *(const float4*)&g_qfull[f * 4];
    v.x *= scale; v.y *= scale; v.z *= scale; v.w *= scale;
    uint32_t h0, l0, h1, l1;
    split_pair(v.x, v.y, h0, l0);
    split_pair(v.z, v.w, h1, l1);
    ((uint2*)g_qh)[f] = make_uint2(h0, h1);
    ((uint2*)g_ql)[f] = make_uint2(l0, l1);
}

// K split: g_kvfull K-slice -> g_kh/g_kl [row][h*192+c]
__global__ __launch_bounds__(256) void ksplit_kernel()
{
    size_t f = (size_t)blockIdx.x * 256 + threadIdx.x;   // unit = 4 floats
    int c4 = (int)(f % 48);
    int h  = (int)((f / 48) % NH);
    int row = (int)(f / 768);
    float4 v = *(const float4*)&g_kvfull[(size_t)row * KVFD + h * KVD + c4 * 4];
    uint32_t h0, l0, h1, l1;
    split_pair(v.x, v.y, h0, l0);
    split_pair(v.z, v.w, h1, l1);
    size_t o = ((size_t)row * (NH*DQK) + h * DQK + c4 * 4) >> 2;   // uint2 index
    ((uint2*)g_kh)[o] = make_uint2(h0, h1);
    ((uint2*)g_kl)[o] = make_uint2(l0, l1);
}

// V transpose+split: g_kvfull V-slice [s][d] -> g_vth/g_vtl [bh][d][s]
__global__ __launch_bounds__(256) void vtsplit_kernel()
{
    __shared__ float tile[32][33];
    int s0 = blockIdx.x * 32, d0 = blockIdx.y * 32, bh = blockIdx.z;
    int b = bh >> 4, h = bh & 15;
    int tx = threadIdx.x, ty = threadIdx.y;
#pragma unroll
    for (int i = ty; i < 32; i += 8)
        tile[i][tx] = g_kvfull[(size_t)(b * S_ + s0 + i) * KVFD + h * KVD + DH + DR + d0 + tx];
    __syncthreads();
#pragma unroll
    for (int i = ty; i < 32; i += 8) {
        float v = tile[tx][i];
        uint32_t bbits = __float_as_uint(v);
        float res = v - __uint_as_float(bbits & 0xFFFF0000u);
        size_t o = ((size_t)bh * DH + d0 + i) * S_ + s0 + tx;
        g_vth[o] = (unsigned short)(bbits >> 16);
        g_vtl[o] = (unsigned short)(__float_as_uint(res) >> 16);
    }
}

// ---------------------------------------------------------------------------
// HMMA flash attention (causal): BM=128, BN=64, 8 warps (16 q-rows each).
// Split-bf16 3-term QK and PV; P stays in registers (C-frag == A-frag layout).
// ---------------------------------------------------------------------------
#define QW 100                 // Q/K smem row stride in words (== 4 mod 32)
#define VW 36                  // VT smem row stride in words  (== 4 mod 32)
#define SM_QH  0
#define SM_QL  12800
#define SM_KH  25600
#define SM_KL  32000
#define SM_VTH 38400
#define SM_VTL 43008
#define ATTN_SMEM_BYTES (47616 * 4)    // 190,464 B

__global__ __launch_bounds__(256, 1) void attn_mma_kernel()
{
    extern __shared__ uint32_t smw[];
    const int qt  = gridDim.x - 1 - blockIdx.x;   // long blocks first
    const int h   = blockIdx.y;
    const int b   = blockIdx.z;
    const int tid = threadIdx.x;
    const int lane = tid & 31, wid = tid >> 5;
    const int g = lane >> 2, t = lane & 3;
    const int qs0 = qt * 128;
    const int mr  = wid * 16;
    const int bh  = b * NH + h;

    const uint32_t sbase = (uint32_t)__cvta_generic_to_shared(smw);
    // ldmatrix lane addresses (bytes)
    const uint32_t aQh = sbase + (SM_QH + (mr + (lane & 15)) * QW + ((lane >> 4) << 2)) * 4;
    const uint32_t aQl = aQh + (SM_QL - SM_QH) * 4;
    const int      bRow = (lane & 7) + ((lane >> 4) & 1) * 8;
    const uint32_t bWrd = ((lane >> 3) & 1) * 4;
    const uint32_t aKh = sbase + (SM_KH + bRow * QW + bWrd) * 4;
    const uint32_t aKl = aKh + (SM_KL - SM_KH) * 4;
    const uint32_t aVh = sbase + (SM_VTH + bRow * VW + bWrd) * 4;
    const uint32_t aVl = aVh + (SM_VTL - SM_VTH) * 4;

    // Stage Q (hi/lo): 128 rows x 24 uint4 per plane
    {
        const uint4* qh = (const uint4*)(g_qh + (size_t)(b * S_ + qs0) * (NH*DQK) + h * DQK);
        const uint4* ql = (const uint4*)(g_ql + (size_t)(b * S_ + qs0) * (NH*DQK) + h * DQK);
        for (int f = tid; f < 128 * 24; f += 256) {
            int r = f / 24, w = f % 24;
            *(uint4*)(smw + SM_QH + r * QW + w * 4) = qh[(size_t)r * 384 + w];
            *(uint4*)(smw + SM_QL + r * QW + w * 4) = ql[(size_t)r * 384 + w];
        }
    }

    float m0 = -1e30f, m1 = -1e30f, l0 = 0.f, l1 = 0.f;
    float o[16][4];
#pragma unroll
    for (int nt = 0; nt < 16; nt++)
#pragma unroll
        for (int e = 0; e < 4; e++) o[nt][e] = 0.f;

    for (int kt = 0; kt <= qs0 + 64; kt += 64) {
        __syncthreads();   // previous compute done before restaging
        // Stage K tile (64 rows x 24 uint4 per plane)
        {
            const uint4* kh = (const uint4*)(g_kh + (size_t)(b * S_ + kt) * (NH*DQK) + h * DQK);
            const uint4* kl = (const uint4*)(g_kl + (size_t)(b * S_ + kt) * (NH*DQK) + h * DQK);
            for (int f = tid; f < 64 * 24; f += 256) {
                int r = f / 24, w = f % 24;
                *(uint4*)(smw + SM_KH + r * QW + w * 4) = kh[(size_t)r * 384 + w];
                *(uint4*)(smw + SM_KL + r * QW + w * 4) = kl[(size_t)r * 384 + w];
            }
        }
        // Stage VT tile (128 dh-rows x 8 uint4 per plane)
        {
            for (int f = tid; f < 128 * 8; f += 256) {
                int d = f / 8, w = f % 8;
                const uint4* vh = (const uint4*)(g_vth + ((size_t)bh * DH + d) * S_ + kt);
                const uint4* vl = (const uint4*)(g_vtl + ((size_t)bh * DH + d) * S_ + kt);
                *(uint4*)(smw + SM_VTH + d * VW + w * 4) = vh[w];
                *(uint4*)(smw + SM_VTL + d * VW + w * 4) = vl[w];
            }
        }
        __syncthreads();

        if (kt > qs0 + mr + 15) continue;   // warp tile fully masked (warp-uniform)

        // ---- QK: S = Q K^T, 3-term split ----
        float s[8][4];
#pragma unroll
        for (int nt = 0; nt < 8; nt++)
#pragma unroll
            for (int e = 0; e < 4; e++) s[nt][e] = 0.f;

#pragma unroll
        for (int c = 0; c < 12; c++) {
            uint32_t ah[4], al[4];
            ldsm4(ah, aQh + c * 32);
            ldsm4(al, aQl + c * 32);
#pragma unroll
            for (int q = 0; q < 4; q++) {
                uint32_t kh[4], kl[4];
                ldsm4(kh, aKh + q * (16 * QW * 4) + c * 32);
                ldsm4(kl, aKl + q * (16 * QW * 4) + c * 32);
                mma_bf16(s[2*q],   ah, kh);     mma_bf16(s[2*q],   ah, kl);
                mma_bf16(s[2*q],   al, kh);
                mma_bf16(s[2*q+1], ah, kh + 2); mma_bf16(s[2*q+1], ah, kl + 2);
                mma_bf16(s[2*q+1], al, kh + 2);
            }
        }

        // causal mask (diagonal-straddling tiles only)
        if (kt >= qs0) {
            int r0 = qs0 + mr + g, r1 = r0 + 8;
#pragma unroll
            for (int nt = 0; nt < 8; nt++) {
                int c0 = kt + nt * 8 + 2 * t;
                if (c0 > r0)     s[nt][0] = -1e30f;
                if (c0 + 1 > r0) s[nt][1] = -1e30f;
                if (c0 > r1)     s[nt][2] = -1e30f;
                if (c0 + 1 > r1) s[nt][3] = -1e30f;
            }
        }

        // ---- online softmax on fragments ----
        float rm0 = -1e30f, rm1 = -1e30f;
#pragma unroll
        for (int nt = 0; nt < 8; nt++) {
            rm0 = fmaxf(rm0, fmaxf(s[nt][0], s[nt][1]));
            rm1 = fmaxf(rm1, fmaxf(s[nt][2], s[nt][3]));
        }
        rm0 = fmaxf(rm0, __shfl_xor_sync(0xffffffffu, rm0, 1));
        rm0 = fmaxf(rm0, __shfl_xor_sync(0xffffffffu, rm0, 2));
        rm1 = fmaxf(rm1, __shfl_xor_sync(0xffffffffu, rm1, 1));
        rm1 = fmaxf(rm1, __shfl_xor_sync(0xffffffffu, rm1, 2));
        float mn0 = fmaxf(m0, rm0), mn1 = fmaxf(m1, rm1);
        float corr0 = __expf(m0 - mn0), corr1 = __expf(m1 - mn1);
        m0 = mn0; m1 = mn1;

        float rs0 = 0.f, rs1 = 0.f;
#pragma unroll
        for (int nt = 0; nt < 8; nt++) {
            s[nt][0] = __expf(s[nt][0] - mn0);
            s[nt][1] = __expf(s[nt][1] - mn0);
            s[nt][2] = __expf(s[nt][2] - mn1);
            s[nt][3] = __expf(s[nt][3] - mn1);
            rs0 += s[nt][0] + s[nt][1];
            rs1 += s[nt][2] + s[nt][3];
        }
        rs0 += __shfl_xor_sync(0xffffffffu, rs0, 1);
        rs0 += __shfl_xor_sync(0xffffffffu, rs0, 2);
        rs1 += __shfl_xor_sync(0xffffffffu, rs1, 1);
        rs1 += __shfl_xor_sync(0xffffffffu, rs1, 2);
        l0 = l0 * corr0 + rs0;
        l1 = l1 * corr1 + rs1;

#pragma unroll
        for (int nt = 0; nt < 16; nt++) {
            o[nt][0] *= corr0; o[nt][1] *= corr0;
            o[nt][2] *= corr1; o[nt][3] *= corr1;
        }

        // ---- pack P into split bf16 A-fragments (registers only) ----
        uint32_t php[8][2], plp[8][2];
#pragma unroll
        for (int nt = 0; nt < 8; nt++) {
            split_pair(s[nt][0], s[nt][1], php[nt][0], plp[nt][0]);
            split_pair(s[nt][2], s[nt][3], php[nt][1], plp[nt][1]);
        }

        // ---- PV: O += P V, 3-term split ----
#pragma unroll
        for (int kc = 0; kc < 4; kc++) {
            uint32_t pah[4] = {php[2*kc][0], php[2*kc][1], php[2*kc+1][0], php[2*kc+1][1]};
            uint32_t pal[4] = {plp[2*kc][0], plp[2*kc][1], plp[2*kc+1][0], plp[2*kc+1][1]};
#pragma unroll
            for (int vq = 0; vq < 8; vq++) {
                uint32_t vh[4], vl[4];
                ldsm4(vh, aVh + vq * (16 * VW * 4) + kc * 32);
                ldsm4(vl, aVl + vq * (16 * VW * 4) + kc * 32);
                mma_bf16(o[2*vq],   pah, vh);     mma_bf16(o[2*vq],   pah, vl);
                mma_bf16(o[2*vq],   pal, vh);
                mma_bf16(o[2*vq+1], pah, vh + 2); mma_bf16(o[2*vq+1], pah, vl + 2);
                mma_bf16(o[2*vq+1], pal, vh + 2);
            }
        }
    }

    // ---- finalize + store ----
    float inv0 = 1.f / l0, inv1 = 1.f / l1;
    int row0 = b * S_ + qs0 + mr + g;
#pragma unroll
    for (int nt = 0; nt < 16; nt++) {
        int col = h * DH + nt * 8 + 2 * t;
        *(float2*)&g_ctx[(size_t)row0 * DMODEL + col] =
            make_float2(o[nt][0] * inv0, o[nt][1] * inv0);
        *(float2*)&g_ctx[(size_t)(row0 + 8) * DMODEL + col] =
            make_float2(o[nt][2] * inv1, o[nt][3] * inv1);
    }
}

// ---------------------------------------------------------------------------
// Launch
// ---------------------------------------------------------------------------
extern "C" void kernel_launch(void* const* d_in, const int* in_sizes, int n_in,
                              void* d_out, int out_size)
{
    (void)in_sizes; (void)n_in; (void)out_size;
    const float* x    = (const float*)d_in[0];
    const float* Wkvd = (const float*)d_in[1];
    const float* Wkvu = (const float*)d_in[2];
    const float* Wqd  = (const float*)d_in[3];
    const float* Wqu  = (const float*)d_in[4];
    const float* Wo   = (const float*)d_in[5];
    float* out = (float*)d_out;

    float *kvlat, *qlat, *kvfull, *qfull, *ctx;
    unsigned short *wkvdH, *wkvdL, *wqdH, *wqdL, *wkvuH, *wkvuL, *wquH, *wquL, *woH, *woL;
    cudaGetSymbolAddress((void**)&kvlat,  g_kvlat);
    cudaGetSymbolAddress((void**)&qlat,   g_qlat);
    cudaGetSymbolAddress((void**)&kvfull, g_kvfull);
    cudaGetSymbolAddress((void**)&qfull,  g_qfull);
    cudaGetSymbolAddress((void**)&ctx,    g_ctx);
    cudaGetSymbolAddress((void**)&wkvdH,  g_wkvd_h);
    cudaGetSymbolAddress((void**)&wkvdL,  g_wkvd_l);
    cudaGetSymbolAddress((void**)&wqdH,   g_wqd_h);
    cudaGetSymbolAddress((void**)&wqdL,   g_wqd_l);
    cudaGetSymbolAddress((void**)&wkvuH,  g_wkvu_h);
    cudaGetSymbolAddress((void**)&wkvuL,  g_wkvu_l);
    cudaGetSymbolAddress((void**)&wquH,   g_wqu_h);
    cudaGetSymbolAddress((void**)&wquL,   g_wqu_l);
    cudaGetSymbolAddress((void**)&woH,    g_wo_h);
    cudaGetSymbolAddress((void**)&woL,    g_wo_l);

    dim3 tt(32, 8);
    transpose_split_kernel<<<dim3(DLAT / 32, DMODEL / 32), tt>>>(Wkvd, wkvdH, wkvdL, DMODEL, DLAT);
    transpose_split_kernel<<<dim3(DLAT / 32, DMODEL / 32), tt>>>(Wqd,  wqdH,  wqdL,  DMODEL, DLAT);
    transpose_split_kernel<<<dim3(KVFD / 32, DLAT / 32),   tt>>>(Wkvu, wkvuH, wkvuL, DLAT,  KVFD);
    transpose_split_kernel<<<dim3(QFD  / 32, DLAT / 32),   tt>>>(Wqu,  wquH,  wquL,  DLAT,  QFD);
    transpose_split_kernel<<<dim3(DMODEL / 32, DMODEL / 32), tt>>>(Wo, woH,   woL,   DMODEL, DMODEL);

    dim3 t(256);
    hmma_gemm<<<dim3(DLAT / 128, ROWS / 128), t>>>(x, wkvdH, wkvdL, kvlat, ROWS, DLAT, DMODEL);
    hmma_gemm<<<dim3(DLAT / 128, ROWS / 128), t>>>(x, wqdH,  wqdL,  qlat,  ROWS, DLAT, DMODEL);
    hmma_gemm<<<dim3(KVFD / 128, ROWS / 128), t>>>(kvlat, wkvuH, wkvuL, kvfull, ROWS, KVFD, DLAT);
    hmma_gemm<<<dim3(QFD  / 128, ROWS / 128), t>>>(qlat,  wquH,  wquL,  qfull,  ROWS, QFD,  DLAT);

    rope_kernel<<<ROWS, 512>>>();

    // split Q/K/V into bf16 hi/lo planes
    qsplit_kernel<<<(ROWS * (size_t)QFD / 4) / 256, 256>>>();
    ksplit_kernel<<<(ROWS * (size_t)NH * 48) / 256, 256>>>();
    vtsplit_kernel<<<dim3(S_ / 32, DH / 32, B_ * NH), tt>>>();

    cudaFuncSetAttribute(attn_mma_kernel, cudaFuncAttributeMaxDynamicSharedMemorySize, ATTN_SMEM_BYTES);
    attn_mma_kernel<<<dim3(S_ / 128, NH, B_), 256, ATTN_SMEM_BYTES>>>();

    hmma_gemm<<<dim3(DMODEL / 128, ROWS / 128), t>>>(ctx, woH, woL, out, ROWS, DMODEL, DMODEL);
}

// round 11
// speedup vs baseline: 3.1484x; 1.1043x over previous
#include <cuda_runtime.h>
#include <cuda_bf16.h>
#include <math.h>
#include <stdint.h>

// Problem constants
#define B_      2
#define S_      2048
#define DMODEL  2048
#define NH      16
#define DH      128
#define DLAT    512
#define DR      64
#define DQK     192            // DH + DR
#define KVD     320            // DH + DR + DH
#define QFD     3072           // NH * DQK
#define KVFD    5120           // NH * KVD
#define ROWS    (B_*S_)        // 4096

// ---- warp-level bf16 MMA (sm_80+, works at compute_100) ----
__device__ __forceinline__ void mma_bf16(float* c, const uint32_t* a, const uint32_t* b) {
    asm("mma.sync.aligned.m16n8k16.row.col.f32.bf16.bf16.f32 "
        "{%0,%1,%2,%3}, {%4,%5,%6,%7}, {%8,%9}, {%0,%1,%2,%3};"
        : "+f"(c[0]), "+f"(c[1]), "+f"(c[2]), "+f"(c[3])
        : "r"(a[0]), "r"(a[1]), "r"(a[2]), "r"(a[3]), "r"(b[0]), "r"(b[1]));
}
__device__ __forceinline__ void ldsm4(uint32_t* r, uint32_t a) {
    asm volatile("ldmatrix.sync.aligned.m8n8.x4.shared.b16 {%0,%1,%2,%3}, [%4];"
        : "=r"(r[0]), "=r"(r[1]), "=r"(r[2]), "=r"(r[3]) : "r"(a));
}

// Scratch (device globals: allocation-free contract)
__device__ float g_kvlat[(size_t)ROWS * DLAT];
__device__ float g_qlat [(size_t)ROWS * DLAT];
__device__ float g_kvfull[(size_t)ROWS * KVFD];
__device__ float g_qfull [(size_t)ROWS * QFD];
__device__ float g_ctx   [(size_t)ROWS * DMODEL];
// Weight planes: transposed [N][K], split into bf16 hi/lo
__device__ unsigned short g_wkvd_h[(size_t)DLAT * DMODEL], g_wkvd_l[(size_t)DLAT * DMODEL];
__device__ unsigned short g_wqd_h [(size_t)DLAT * DMODEL], g_wqd_l [(size_t)DLAT * DMODEL];
__device__ unsigned short g_wkvu_h[(size_t)KVFD * DLAT],   g_wkvu_l[(size_t)KVFD * DLAT];
__device__ unsigned short g_wqu_h [(size_t)QFD  * DLAT],   g_wqu_l [(size_t)QFD  * DLAT];
__device__ unsigned short g_wo_h  [(size_t)DMODEL*DMODEL], g_wo_l  [(size_t)DMODEL*DMODEL];
// Attention operand planes (bf16 hi/lo), post-rope
__device__ unsigned short g_qh [(size_t)ROWS * (NH*DQK)], g_ql [(size_t)ROWS * (NH*DQK)];
__device__ unsigned short g_kh [(size_t)ROWS * (NH*DQK)], g_kl [(size_t)ROWS * (NH*DQK)];
__device__ unsigned short g_vth[(size_t)B_*NH*DH * S_],   g_vtl[(size_t)B_*NH*DH * S_];

// ---------------------------------------------------------------------------
// Transpose + bf16 split (weights): in [R][C] fp32 -> hi/lo [C][R] bf16.
// ---------------------------------------------------------------------------
__global__ __launch_bounds__(256) void transpose_split_kernel(
    const float* __restrict__ in, unsigned short* __restrict__ oh,
    unsigned short* __restrict__ ol, int R, int C)
{
    __shared__ float tile[32][33];
    int c0 = blockIdx.x * 32, r0 = blockIdx.y * 32;
    int tx = threadIdx.x, ty = threadIdx.y;
#pragma unroll
    for (int i = ty; i < 32; i += 8)
        tile[i][tx] = in[(size_t)(r0 + i) * C + c0 + tx];
    __syncthreads();
#pragma unroll
    for (int i = ty; i < 32; i += 8) {
        float v = tile[tx][i];
        uint32_t b = __float_as_uint(v);
        float res = v - __uint_as_float(b & 0xFFFF0000u);
        size_t o = (size_t)(c0 + i) * R + r0 + tx;
        oh[o] = (unsigned short)(b >> 16);
        ol[o] = (unsigned short)(__float_as_uint(res) >> 16);
    }
}

// ---------------------------------------------------------------------------
// HMMA split-bf16 GEMM: fragments via ldmatrix.x4 (12 LDSM/warp/chunk).
// 128x128 tile, 256 thr, 8 warps (2x4), warp tile 64x32, K-chunk 16,
// double-buffered smem. 3 mmas per k16 subtile (hh + hl + lh).
// ---------------------------------------------------------------------------
#define PSTR 12
#define PLW  (128 * PSTR)
#define STW  (4 * PLW)

__global__ __launch_bounds__(256) void hmma_gemm(
    const float* __restrict__ A, const unsigned short* __restrict__ Bh,
    const unsigned short* __restrict__ Bl, float* __restrict__ C,
    int M, int N, int K)
{
    __shared__ __align__(16) uint32_t smw[2 * STW];

    const int tid  = threadIdx.x;
    const int lane = tid & 31, wid = tid >> 5;
    const int g = lane >> 2, t = lane & 3;
    const int wm = wid >> 2, wn = wid & 3;
    const int bx = blockIdx.x, by = blockIdx.y;

    const float* Ab = A + (size_t)by * 128 * K;
    const unsigned short* Bhb = Bh + (size_t)bx * 128 * K;
    const unsigned short* Blb = Bl + (size_t)bx * 128 * K;

    float acc[4][4][4];
#pragma unroll
    for (int mt = 0; mt < 4; mt++)
#pragma unroll
        for (int nt = 0; nt < 4; nt++)
#pragma unroll
            for (int q = 0; q < 4; q++) acc[mt][nt][q] = 0.f;

    const int ar = tid >> 2, ac4 = tid & 3;
    const int br = tid >> 1, bh2 = tid & 1;

    // ldmatrix lane base addresses (stage 0, hi planes); byte units
    const uint32_t sb0 = (uint32_t)__cvta_generic_to_shared(smw);
    const int arow0 = wm * 64 + (lane & 7) + ((lane >> 3) & 1) * 8;
    const uint32_t aAh = sb0 + (uint32_t)(arow0 * PSTR + (lane >> 4) * 4) * 4;
    const uint32_t aAl = aAh + PLW * 4;
    const int brow0 = wn * 32 + (lane & 7) + (lane >> 4) * 8;
    const uint32_t aBh = sb0 + (uint32_t)(2 * PLW + brow0 * PSTR + ((lane >> 3) & 1) * 4) * 4;
    const uint32_t aBl = aBh + PLW * 4;

    float4 av[2]; uint4 bhv, blv;

    // ---- prologue: global load + split + store stage 0 ----
    av[0] = *(const float4*)&Ab[(size_t)ar * K + ac4 * 4];
    av[1] = *(const float4*)&Ab[(size_t)(ar + 64) * K + ac4 * 4];
    bhv = *(const uint4*)&Bhb[(size_t)br * K + bh2 * 8];
    blv = *(const uint4*)&Blb[(size_t)br * K + bh2 * 8];
    {
        uint32_t* Ah = smw;  uint32_t* Al = Ah + PLW;
        uint32_t* Bhs = Al + PLW; uint32_t* Bls = Bhs + PLW;
#pragma unroll
        for (int i = 0; i < 2; i++) {
            float4 v = av[i];
            uint32_t xb = __float_as_uint(v.x), yb = __float_as_uint(v.y);
            uint32_t zb = __float_as_uint(v.z), wb = __float_as_uint(v.w);
            float rx = v.x - __uint_as_float(xb & 0xFFFF0000u);
            float ry = v.y - __uint_as_float(yb & 0xFFFF0000u);
            float rz = v.z - __uint_as_float(zb & 0xFFFF0000u);
            float rw = v.w - __uint_as_float(wb & 0xFFFF0000u);
            int base = (ar + 64 * i) * PSTR + ac4 * 2;
            Ah[base]     = __byte_perm(xb, yb, 0x7632);
            Ah[base + 1] = __byte_perm(zb, wb, 0x7632);
            Al[base]     = __byte_perm(__float_as_uint(rx), __float_as_uint(ry), 0x7632);
            Al[base + 1] = __byte_perm(__float_as_uint(rz), __float_as_uint(rw), 0x7632);
        }
        int bb = br * PSTR + bh2 * 4;
        *(uint4*)&Bhs[bb] = bhv;
        *(uint4*)&Bls[bb] = blv;
    }
    __syncthreads();

    const int NS = K / 16;
    for (int sI = 0; sI < NS; sI++) {
        const int cur = sI & 1;
        const bool more = (sI + 1) < NS;
        if (more) {
            const int k0 = (sI + 1) * 16;
            av[0] = *(const float4*)&Ab[(size_t)ar * K + k0 + ac4 * 4];
            av[1] = *(const float4*)&Ab[(size_t)(ar + 64) * K + k0 + ac4 * 4];
            bhv = *(const uint4*)&Bhb[(size_t)br * K + k0 + bh2 * 8];
            blv = *(const uint4*)&Blb[(size_t)br * K + k0 + bh2 * 8];
        }

        // ---- compute on stage cur (ldmatrix fragments) ----
        {
            const uint32_t so = (uint32_t)cur * (STW * 4);

            uint32_t bfh[4][2], bfl[4][2];
            {
                uint32_t r[4];
                ldsm4(r, aBh + so);                              // nt 0,1 hi
                bfh[0][0] = r[0]; bfh[0][1] = r[1];
                bfh[1][0] = r[2]; bfh[1][1] = r[3];
                ldsm4(r, aBh + so + 16 * PSTR * 4);              // nt 2,3 hi
                bfh[2][0] = r[0]; bfh[2][1] = r[1];
                bfh[3][0] = r[2]; bfh[3][1] = r[3];
                ldsm4(r, aBl + so);                              // nt 0,1 lo
                bfl[0][0] = r[0]; bfl[0][1] = r[1];
                bfl[1][0] = r[2]; bfl[1][1] = r[3];
                ldsm4(r, aBl + so + 16 * PSTR * 4);              // nt 2,3 lo
                bfl[2][0] = r[0]; bfl[2][1] = r[1];
                bfl[3][0] = r[2]; bfl[3][1] = r[3];
            }
#pragma unroll
            for (int mt = 0; mt < 4; mt++) {
                uint32_t ah[4], al[4];
                ldsm4(ah, aAh + so + mt * (16 * PSTR * 4));
                ldsm4(al, aAl + so + mt * (16 * PSTR * 4));
#pragma unroll
                for (int nt = 0; nt < 4; nt++) {
                    mma_bf16(acc[mt][nt], ah, bfh[nt]);
                    mma_bf16(acc[mt][nt], ah, bfl[nt]);
                    mma_bf16(acc[mt][nt], al, bfh[nt]);
                }
            }
        }

        if (more) {
            uint32_t* Ah = smw + (cur ^ 1) * STW;
            uint32_t* Al = Ah + PLW;
            uint32_t* Bhs = Al + PLW;
            uint32_t* Bls = Bhs + PLW;
#pragma unroll
            for (int i = 0; i < 2; i++) {
                float4 v = av[i];
                uint32_t xb = __float_as_uint(v.x), yb = __float_as_uint(v.y);
                uint32_t zb = __float_as_uint(v.z), wb = __float_as_uint(v.w);
                float rx = v.x - __uint_as_float(xb & 0xFFFF0000u);
                float ry = v.y - __uint_as_float(yb & 0xFFFF0000u);
                float rz = v.z - __uint_as_float(zb & 0xFFFF0000u);
                float rw = v.w - __uint_as_float(wb & 0xFFFF0000u);
                int base = (ar + 64 * i) * PSTR + ac4 * 2;
                Ah[base]     = __byte_perm(xb, yb, 0x7632);
                Ah[base + 1] = __byte_perm(zb, wb, 0x7632);
                Al[base]     = __byte_perm(__float_as_uint(rx), __float_as_uint(ry), 0x7632);
                Al[base + 1] = __byte_perm(__float_as_uint(rz), __float_as_uint(rw), 0x7632);
            }
            int bb = br * PSTR + bh2 * 4;
            *(uint4*)&Bhs[bb] = bhv;
            *(uint4*)&Bls[bb] = blv;
        }
        __syncthreads();
    }

#pragma unroll
    for (int mt = 0; mt < 4; mt++) {
        int row = by * 128 + wm * 64 + mt * 16 + g;
#pragma unroll
        for (int nt = 0; nt < 4; nt++) {
            int col = bx * 128 + wn * 32 + nt * 8 + 2 * t;
            *(float2*)&C[(size_t)row * N + col]       = make_float2(acc[mt][nt][0], acc[mt][nt][1]);
            *(float2*)&C[(size_t)(row + 8) * N + col] = make_float2(acc[mt][nt][2], acc[mt][nt][3]);
        }
    }
}

// ---------------------------------------------------------------------------
// Split helpers: fp32 -> bf16 hi/lo words
// ---------------------------------------------------------------------------
__device__ __forceinline__ void split_pair(float a, float b, uint32_t& hw, uint32_t& lw) {
    uint32_t ua = __float_as_uint(a), ub = __float_as_uint(b);
    float ra = a - __uint_as_float(ua & 0xFFFF0000u);
    float rb = b - __uint_as_float(ub & 0xFFFF0000u);
    hw = __byte_perm(ua, ub, 0x7632);
    lw = __byte_perm(__float_as_uint(ra), __float_as_uint(rb), 0x7632);
}

// Apply RoPE to a float4 at dim c (>=128) of one head's 192-dim q/k vector.
// partner = float4 at c+32 (if j<32) or c-32 (if j>=32).
__device__ __forceinline__ float4 rope4(float4 v, float4 p, int c, int s) {
    int j = c - 128;
    bool first = (j < 32);
    int jb = first ? j : (j - 32);
    float4 r;
#pragma unroll
    for (int e = 0; e < 4; e++) {
        float inv = __expf(-(float)(jb + e) * (9.210340371976184f / 32.f));
        float ang = (float)s * inv;
        float cs, sn;
        __sincosf(ang, &sn, &cs);
        float ve = (e == 0) ? v.x : (e == 1) ? v.y : (e == 2) ? v.z : v.w;
        float pe = (e == 0) ? p.x : (e == 1) ? p.y : (e == 2) ? p.z : p.w;
        float o = first ? (ve * cs - pe * sn) : (ve * cs + pe * sn);
        if (e == 0) r.x = o; else if (e == 1) r.y = o; else if (e == 2) r.z = o; else r.w = o;
    }
    return r;
}

// Q: rope + scale + split, g_qfull -> g_qh/g_ql (same layout)
__global__ __launch_bounds__(256) void qsplit_kernel()
{
    const float scale = 0.07216878364870323f;   // 1/sqrt(192)
    size_t f = (size_t)blockIdx.x * 256 + threadIdx.x;   // float4 index
    int w = (int)(f % 768);
    int c = (w % 48) * 4;
    int row = (int)(f / 768);
    int s = row & (S_ - 1);
    float4 v = *(const float4*)&g_qfull[f * 4];
    if (c >= 128) {
        float4 p = (c < 160) ? *(const float4*)&g_qfull[f * 4 + 32]
                             : *(const float4*)&g_qfull[f * 4 - 32];
        v = rope4(v, p, c, s);
    }
    v.x *= scale; v.y *= scale; v.z *= scale; v.w *= scale;
    uint32_t h0, l0, h1, l1;
    split_pair(v.x, v.y, h0, l0);
    split_pair(v.z, v.w, h1, l1);
    ((uint2*)g_qh)[f] = make_uint2(h0, h1);
    ((uint2*)g_ql)[f] = make_uint2(l0, l1);
}

// K: rope + split, g_kvfull K-slice -> g_kh/g_kl [row][h*192+c]
__global__ __launch_bounds__(256) void ksplit_kernel()
{
    size_t f = (size_t)blockIdx.x * 256 + threadIdx.x;   // unit = 4 floats
    int c4 = (int)(f % 48);
    int h  = (int)((f / 48) % NH);
    int row = (int)(f / 768);
    int s = row & (S_ - 1);
    int c = c4 * 4;
    size_t base = (size_t)row * KVFD + h * KVD + c;
    float4 v = *(const float4*)&g_kvfull[base];
    if (c >= 128) {
        float4 p = (c < 160) ? *(const float4*)&g_kvfull[base + 32]
                             : *(const float4*)&g_kvfull[base - 32];
        v = rope4(v, p, c, s);
    }
    uint32_t h0, l0, h1, l1;
    split_pair(v.x, v.y, h0, l0);
    split_pair(v.z, v.w, h1, l1);
    size_t o = ((size_t)row * (NH*DQK) + h * DQK + c) >> 2;
    ((uint2*)g_kh)[o] = make_uint2(h0, h1);
    ((uint2*)g_kl)[o] = make_uint2(l0, l1);
}

// V transpose+split: g_kvfull V-slice [s][d] -> g_vth/g_vtl [bh][d][s]
__global__ __launch_bounds__(256) void vtsplit_kernel()
{
    __shared__ float tile[32][33];
    int s0 = blockIdx.x * 32, d0 = blockIdx.y * 32, bh = blockIdx.z;
    int b = bh >> 4, h = bh & 15;
    int tx = threadIdx.x, ty = threadIdx.y;
#pragma unroll
    for (int i = ty; i < 32; i += 8)
        tile[i][tx] = g_kvfull[(size_t)(b * S_ + s0 + i) * KVFD + h * KVD + DH + DR + d0 + tx];
    __syncthreads();
#pragma unroll
    for (int i = ty; i < 32; i += 8) {
        float v = tile[tx][i];
        uint32_t bbits = __float_as_uint(v);
        float res = v - __uint_as_float(bbits & 0xFFFF0000u);
        size_t o = ((size_t)bh * DH + d0 + i) * S_ + s0 + tx;
        g_vth[o] = (unsigned short)(bbits >> 16);
        g_vtl[o] = (unsigned short)(__float_as_uint(res) >> 16);
    }
}

// ---------------------------------------------------------------------------
// HMMA flash attention (causal): BM=128, BN=64, 8 warps (16 q-rows each).
// Split-bf16 3-term QK and PV; P stays in registers (C-frag == A-frag layout).
// ---------------------------------------------------------------------------
#define QW 100                 // Q/K smem row stride in words (== 4 mod 32)
#define VW 36                  // VT smem row stride in words  (== 4 mod 32)
#define SM_QH  0
#define SM_QL  12800
#define SM_KH  25600
#define SM_KL  32000
#define SM_VTH 38400
#define SM_VTL 43008
#define ATTN_SMEM_BYTES (47616 * 4)    // 190,464 B

__global__ __launch_bounds__(256, 1) void attn_mma_kernel()
{
    extern __shared__ uint32_t smw[];
    const int qt  = gridDim.x - 1 - blockIdx.x;   // long blocks first
    const int h   = blockIdx.y;
    const int b   = blockIdx.z;
    const int tid = threadIdx.x;
    const int lane = tid & 31, wid = tid >> 5;
    const int g = lane >> 2, t = lane & 3;
    const int qs0 = qt * 128;
    const int mr  = wid * 16;
    const int bh  = b * NH + h;

    const uint32_t sbase = (uint32_t)__cvta_generic_to_shared(smw);
    const uint32_t aQh = sbase + (SM_QH + (mr + (lane & 15)) * QW + ((lane >> 4) << 2)) * 4;
    const uint32_t aQl = aQh + (SM_QL - SM_QH) * 4;
    const int      bRow = (lane & 7) + ((lane >> 4) & 1) * 8;
    const uint32_t bWrd = ((lane >> 3) & 1) * 4;
    const uint32_t aKh = sbase + (SM_KH + bRow * QW + bWrd) * 4;
    const uint32_t aKl = aKh + (SM_KL - SM_KH) * 4;
    const uint32_t aVh = sbase + (SM_VTH + bRow * VW + bWrd) * 4;
    const uint32_t aVl = aVh + (SM_VTL - SM_VTH) * 4;

    // Stage Q (hi/lo): 128 rows x 24 uint4 per plane
    {
        const uint4* qh = (const uint4*)(g_qh + (size_t)(b * S_ + qs0) * (NH*DQK) + h * DQK);
        const uint4* ql = (const uint4*)(g_ql + (size_t)(b * S_ + qs0) * (NH*DQK) + h * DQK);
        for (int f = tid; f < 128 * 24; f += 256) {
            int r = f / 24, w = f % 24;
            *(uint4*)(smw + SM_QH + r * QW + w * 4) = qh[(size_t)r * 384 + w];
            *(uint4*)(smw + SM_QL + r * QW + w * 4) = ql[(size_t)r * 384 + w];
        }
    }

    float m0 = -1e30f, m1 = -1e30f, l0 = 0.f, l1 = 0.f;
    float o[16][4];
#pragma unroll
    for (int nt = 0; nt < 16; nt++)
#pragma unroll
        for (int e = 0; e < 4; e++) o[nt][e] = 0.f;

    for (int kt = 0; kt <= qs0 + 64; kt += 64) {
        __syncthreads();
        {
            const uint4* kh = (const uint4*)(g_kh + (size_t)(b * S_ + kt) * (NH*DQK) + h * DQK);
            const uint4* kl = (const uint4*)(g_kl + (size_t)(b * S_ + kt) * (NH*DQK) + h * DQK);
            for (int f = tid; f < 64 * 24; f += 256) {
                int r = f / 24, w = f % 24;
                *(uint4*)(smw + SM_KH + r * QW + w * 4) = kh[(size_t)r * 384 + w];
                *(uint4*)(smw + SM_KL + r * QW + w * 4) = kl[(size_t)r * 384 + w];
            }
        }
        {
            for (int f = tid; f < 128 * 8; f += 256) {
                int d = f / 8, w = f % 8;
                const uint4* vh = (const uint4*)(g_vth + ((size_t)bh * DH + d) * S_ + kt);
                const uint4* vl = (const uint4*)(g_vtl + ((size_t)bh * DH + d) * S_ + kt);
                *(uint4*)(smw + SM_VTH + d * VW + w * 4) = vh[w];
                *(uint4*)(smw + SM_VTL + d * VW + w * 4) = vl[w];
            }
        }
        __syncthreads();

        if (kt > qs0 + mr + 15) continue;   // warp tile fully masked (warp-uniform)

        // ---- QK: S = Q K^T, 3-term split ----
        float s[8][4];
#pragma unroll
        for (int nt = 0; nt < 8; nt++)
#pragma unroll
            for (int e = 0; e < 4; e++) s[nt][e] = 0.f;

#pragma unroll
        for (int c = 0; c < 12; c++) {
            uint32_t ah[4], al[4];
            ldsm4(ah, aQh + c * 32);
            ldsm4(al, aQl + c * 32);
#pragma unroll
            for (int q = 0; q < 4; q++) {
                uint32_t kh[4], kl[4];
                ldsm4(kh, aKh + q * (16 * QW * 4) + c * 32);
                ldsm4(kl, aKl + q * (16 * QW * 4) + c * 32);
                mma_bf16(s[2*q],   ah, kh);     mma_bf16(s[2*q],   ah, kl);
                mma_bf16(s[2*q],   al, kh);
                mma_bf16(s[2*q+1], ah, kh + 2); mma_bf16(s[2*q+1], ah, kl + 2);
                mma_bf16(s[2*q+1], al, kh + 2);
            }
        }

        // causal mask (diagonal-straddling tiles only)
        if (kt >= qs0) {
            int r0 = qs0 + mr + g, r1 = r0 + 8;
#pragma unroll
            for (int nt = 0; nt < 8; nt++) {
                int c0 = kt + nt * 8 + 2 * t;
                if (c0 > r0)     s[nt][0] = -1e30f;
                if (c0 + 1 > r0) s[nt][1] = -1e30f;
                if (c0 > r1)     s[nt][2] = -1e30f;
                if (c0 + 1 > r1) s[nt][3] = -1e30f;
            }
        }

        // ---- online softmax on fragments ----
        float rm0 = -1e30f, rm1 = -1e30f;
#pragma unroll
        for (int nt = 0; nt < 8; nt++) {
            rm0 = fmaxf(rm0, fmaxf(s[nt][0], s[nt][1]));
            rm1 = fmaxf(rm1, fmaxf(s[nt][2], s[nt][3]));
        }
        rm0 = fmaxf(rm0, __shfl_xor_sync(0xffffffffu, rm0, 1));
        rm0 = fmaxf(rm0, __shfl_xor_sync(0xffffffffu, rm0, 2));
        rm1 = fmaxf(rm1, __shfl_xor_sync(0xffffffffu, rm1, 1));
        rm1 = fmaxf(rm1, __shfl_xor_sync(0xffffffffu, rm1, 2));
        float mn0 = fmaxf(m0, rm0), mn1 = fmaxf(m1, rm1);
        float corr0 = __expf(m0 - mn0), corr1 = __expf(m1 - mn1);
        m0 = mn0; m1 = mn1;

        float rs0 = 0.f, rs1 = 0.f;
#pragma unroll
        for (int nt = 0; nt < 8; nt++) {
            s[nt][0] = __expf(s[nt][0] - mn0);
            s[nt][1] = __expf(s[nt][1] - mn0);
            s[nt][2] = __expf(s[nt][2] - mn1);
            s[nt][3] = __expf(s[nt][3] - mn1);
            rs0 += s[nt][0] + s[nt][1];
            rs1 += s[nt][2] + s[nt][3];
        }
        rs0 += __shfl_xor_sync(0xffffffffu, rs0, 1);
        rs0 += __shfl_xor_sync(0xffffffffu, rs0, 2);
        rs1 += __shfl_xor_sync(0xffffffffu, rs1, 1);
        rs1 += __shfl_xor_sync(0xffffffffu, rs1, 2);
        l0 = l0 * corr0 + rs0;
        l1 = l1 * corr1 + rs1;

#pragma unroll
        for (int nt = 0; nt < 16; nt++) {
            o[nt][0] *= corr0; o[nt][1] *= corr0;
            o[nt][2] *= corr1; o[nt][3] *= corr1;
        }

        // ---- pack P into split bf16 A-fragments (registers only) ----
        uint32_t php[8][2], plp[8][2];
#pragma unroll
        for (int nt = 0; nt < 8; nt++) {
            split_pair(s[nt][0], s[nt][1], php[nt][0], plp[nt][0]);
            split_pair(s[nt][2], s[nt][3], php[nt][1], plp[nt][1]);
        }

        // ---- PV: O += P V, 3-term split ----
#pragma unroll
        for (int kc = 0; kc < 4; kc++) {
            uint32_t pah[4] = {php[2*kc][0], php[2*kc][1], php[2*kc+1][0], php[2*kc+1][1]};
            uint32_t pal[4] = {plp[2*kc][0], plp[2*kc][1], plp[2*kc+1][0], plp[2*kc+1][1]};
#pragma unroll
            for (int vq = 0; vq < 8; vq++) {
                uint32_t vh[4], vl[4];
                ldsm4(vh, aVh + vq * (16 * VW * 4) + kc * 32);
                ldsm4(vl, aVl + vq * (16 * VW * 4) + kc * 32);
                mma_bf16(o[2*vq],   pah, vh);     mma_bf16(o[2*vq],   pah, vl);
                mma_bf16(o[2*vq],   pal, vh);
                mma_bf16(o[2*vq+1], pah, vh + 2); mma_bf16(o[2*vq+1], pah, vl + 2);
                mma_bf16(o[2*vq+1], pal, vh + 2);
            }
        }
    }

    // ---- finalize + store ----
    float inv0 = 1.f / l0, inv1 = 1.f / l1;
    int row0 = b * S_ + qs0 + mr + g;
#pragma unroll
    for (int nt = 0; nt < 16; nt++) {
        int col = h * DH + nt * 8 + 2 * t;
        *(float2*)&g_ctx[(size_t)row0 * DMODEL + col] =
            make_float2(o[nt][0] * inv0, o[nt][1] * inv0);
        *(float2*)&g_ctx[(size_t)(row0 + 8) * DMODEL + col] =
            make_float2(o[nt][2] * inv1, o[nt][3] * inv1);
    }
}

// ---------------------------------------------------------------------------
// Launch
// ---------------------------------------------------------------------------
extern "C" void kernel_launch(void* const* d_in, const int* in_sizes, int n_in,
                              void* d_out, int out_size)
{
    (void)in_sizes; (void)n_in; (void)out_size;
    const float* x    = (const float*)d_in[0];
    const float* Wkvd = (const float*)d_in[1];
    const float* Wkvu = (const float*)d_in[2];
    const float* Wqd  = (const float*)d_in[3];
    const float* Wqu  = (const float*)d_in[4];
    const float* Wo   = (const float*)d_in[5];
    float* out = (float*)d_out;

    float *kvlat, *qlat, *kvfull, *qfull, *ctx;
    unsigned short *wkvdH, *wkvdL, *wqdH, *wqdL, *wkvuH, *wkvuL, *wquH, *wquL, *woH, *woL;
    cudaGetSymbolAddress((void**)&kvlat,  g_kvlat);
    cudaGetSymbolAddress((void**)&qlat,   g_qlat);
    cudaGetSymbolAddress((void**)&kvfull, g_kvfull);
    cudaGetSymbolAddress((void**)&qfull,  g_qfull);
    cudaGetSymbolAddress((void**)&ctx,    g_ctx);
    cudaGetSymbolAddress((void**)&wkvdH,  g_wkvd_h);
    cudaGetSymbolAddress((void**)&wkvdL,  g_wkvd_l);
    cudaGetSymbolAddress((void**)&wqdH,   g_wqd_h);
    cudaGetSymbolAddress((void**)&wqdL,   g_wqd_l);
    cudaGetSymbolAddress((void**)&wkvuH,  g_wkvu_h);
    cudaGetSymbolAddress((void**)&wkvuL,  g_wkvu_l);
    cudaGetSymbolAddress((void**)&wquH,   g_wqu_h);
    cudaGetSymbolAddress((void**)&wquL,   g_wqu_l);
    cudaGetSymbolAddress((void**)&woH,    g_wo_h);
    cudaGetSymbolAddress((void**)&woL,    g_wo_l);

    dim3 tt(32, 8);
    transpose_split_kernel<<<dim3(DLAT / 32, DMODEL / 32), tt>>>(Wkvd, wkvdH, wkvdL, DMODEL, DLAT);
    transpose_split_kernel<<<dim3(DLAT / 32, DMODEL / 32), tt>>>(Wqd,  wqdH,  wqdL,  DMODEL, DLAT);
    transpose_split_kernel<<<dim3(KVFD / 32, DLAT / 32),   tt>>>(Wkvu, wkvuH, wkvuL, DLAT,  KVFD);
    transpose_split_kernel<<<dim3(QFD  / 32, DLAT / 32),   tt>>>(Wqu,  wquH,  wquL,  DLAT,  QFD);
    transpose_split_kernel<<<dim3(DMODEL / 32, DMODEL / 32), tt>>>(Wo, woH,   woL,   DMODEL, DMODEL);

    dim3 t(256);
    hmma_gemm<<<dim3(DLAT / 128, ROWS / 128), t>>>(x, wkvdH, wkvdL, kvlat, ROWS, DLAT, DMODEL);
    hmma_gemm<<<dim3(DLAT / 128, ROWS / 128), t>>>(x, wqdH,  wqdL,  qlat,  ROWS, DLAT, DMODEL);
    hmma_gemm<<<dim3(KVFD / 128, ROWS / 128), t>>>(kvlat, wkvuH, wkvuL, kvfull, ROWS, KVFD, DLAT);
    hmma_gemm<<<dim3(QFD  / 128, ROWS / 128), t>>>(qlat,  wquH,  wquL,  qfull,  ROWS, QFD,  DLAT);

    // rope fused into the split kernels (no separate rope pass)
    qsplit_kernel<<<(ROWS * (size_t)QFD / 4) / 256, 256>>>();
    ksplit_kernel<<<(ROWS * (size_t)NH * 48) / 256, 256>>>();
    vtsplit_kernel<<<dim3(S_ / 32, DH / 32, B_ * NH), tt>>>();

    cudaFuncSetAttribute(attn_mma_kernel, cudaFuncAttributeMaxDynamicSharedMemorySize, ATTN_SMEM_BYTES);
    attn_mma_kernel<<<dim3(S_ / 128, NH, B_), 256, ATTN_SMEM_BYTES>>>();

    hmma_gemm<<<dim3(DMODEL / 128, ROWS / 128), t>>>(ctx, woH, woL, out, ROWS, DMODEL, DMODEL);
}